// round 5
// baseline (speedup 1.0000x reference)
#include <cuda_runtime.h>
#include <cstdint>

#define B_   4
#define N_   2048
#define DIN  128
#define H_   4
#define HD_  32
#define LOG2E 1.4426950408889634f

// ---------------- scratch (no allocs allowed) ----------------
__device__ float    g_h [B_ * N_ * DIN];     // 4 MB
__device__ float    g_ei[B_ * N_ * H_];      // pre-scaled by log2e
__device__ float    g_ej[B_ * N_ * H_];
__device__ unsigned g_adjw[(N_ / 32) * N_];  // [jw][i]  transposed bitmask

__device__ __forceinline__ float ex2f(float x) {
    float r; asm("ex2.approx.ftz.f32 %0, %1;" : "=f"(r) : "f"(x)); return r;
}

// ---------------- kernel 1: h = x @ W^T (8192x128x128) ----------------
#define WT_STRIDE 132
#define GEMM_SMEM ((128 * WT_STRIDE + 64 * 128) * 4)
__global__ void k_gemm(const float* __restrict__ x, const float* __restrict__ W) {
    extern __shared__ float sm[];
    float* Wt = sm;
    float* xs = sm + 128 * WT_STRIDE;
    const int t = threadIdx.x;
    const int row0 = blockIdx.x * 64;
    for (int idx = t; idx < 128 * 128; idx += 256) {
        int c = idx >> 7, k = idx & 127;
        Wt[k * WT_STRIDE + c] = W[idx];
    }
    for (int idx = t; idx < 64 * 128 / 4; idx += 256)
        *(float4*)&xs[idx * 4] = *(const float4*)&x[(size_t)row0 * 128 + idx * 4];
    __syncthreads();
    const int rg = t >> 5, cg = t & 31;
    float acc[8][4];
    #pragma unroll
    for (int r = 0; r < 8; r++) { acc[r][0]=acc[r][1]=acc[r][2]=acc[r][3]=0.f; }
    #pragma unroll 4
    for (int k = 0; k < 128; k++) {
        float4 wv = *(const float4*)&Wt[k * WT_STRIDE + cg * 4];
        #pragma unroll
        for (int r = 0; r < 8; r++) {
            float xv = xs[(rg * 8 + r) * 128 + k];
            acc[r][0] = fmaf(xv, wv.x, acc[r][0]);
            acc[r][1] = fmaf(xv, wv.y, acc[r][1]);
            acc[r][2] = fmaf(xv, wv.z, acc[r][2]);
            acc[r][3] = fmaf(xv, wv.w, acc[r][3]);
        }
    }
    #pragma unroll
    for (int r = 0; r < 8; r++)
        *(float4*)&g_h[(size_t)(row0 + rg * 8 + r) * 128 + cg * 4] =
            make_float4(acc[r][0], acc[r][1], acc[r][2], acc[r][3]);
}

// ---------------- kernel 1b: ei/ej ----------------
__global__ void k_eij(const float* __restrict__ a) {
    __shared__ float as[256];
    const int t = threadIdx.x;
    if (t < 256) as[t] = a[t] * LOG2E;
    __syncthreads();
    const int warp = t >> 5, lane = t & 31;
    const int row = blockIdx.x * 8 + warp;
    float4 hv = *(const float4*)&g_h[(size_t)row * 128 + lane * 4];
    const int hh = lane >> 3, dbase = (lane & 7) * 4;
    const float* a1 = &as[hh * 64];
    const float* a2 = &as[hh * 64 + 32];
    float p1 = hv.x*a1[dbase]+hv.y*a1[dbase+1]+hv.z*a1[dbase+2]+hv.w*a1[dbase+3];
    float p2 = hv.x*a2[dbase]+hv.y*a2[dbase+1]+hv.z*a2[dbase+2]+hv.w*a2[dbase+3];
    #pragma unroll
    for (int o = 1; o < 8; o <<= 1) {
        p1 += __shfl_xor_sync(0xffffffffu, p1, o, 8);
        p2 += __shfl_xor_sync(0xffffffffu, p2, o, 8);
    }
    if ((lane & 7) == 0) { g_ei[row * H_ + hh] = p1; g_ej[row * H_ + hh] = p2; }
}

// ---------------- kernel 2: pack adj ----------------
__global__ void k_pack(const int* __restrict__ adj) {
    const int gw = (blockIdx.x * blockDim.x + threadIdx.x) >> 5;
    const int lane = threadIdx.x & 31;
    const int i = gw >> 6, jw = gw & 63;
    int v = adj[(size_t)i * N_ + jw * 32 + lane];
    unsigned word = __ballot_sync(0xffffffffu, v != 0);
    if (lane == 0) g_adjw[jw * N_ + i] = word;
}

// ---------------- kernel 3: fused masked softmax + aggregation ----------------
// grid (32, H, B), 256 threads. BI = 64, BJ = 128. 4 CTAs/SM target.
// Phase B: 4i x 8d register tile per thread (f32x2 over d), 4-way j-split.
#define ATTN_SMEM ((128*64 + 128*32 + 128 + 256 + 256) * 4)   // ~50.5 KB
__global__ void __launch_bounds__(256, 4) k_attn(float* __restrict__ out) {
    extern __shared__ float sm[];
    float*    pt   = sm;                          // [128 j][64 i]; reused as reduce buf
    float*    hs   = sm + 8192;                   // [128 j][32 d]
    float*    ejs  = hs + 4096;                   // [128]
    unsigned* adjs = (unsigned*)(ejs + 128);      // [4][64]
    float*    zsm  = (float*)(adjs + 256);        // [4][64]

    const int t  = threadIdx.x;
    const int i0 = blockIdx.x * 64;
    const int hh = blockIdx.y;
    const int b  = blockIdx.z;

    // phase-A mapping: i = iA, j quarter = jq (32 j's)
    const int iA = t & 63, jq = t >> 6;
    const float ei_r = g_ei[(b * N_ + i0 + iA) * H_ + hh];
    float zpart = 0.f;

    // phase-B mapping: jh = quarter of j; slot -> (ig: 4 i's, dg: 8 d's)
    const int jh   = t >> 6;
    const int slot = t & 63;
    const int ig   = slot >> 2;       // 0..15 : i = ig*4 .. +4
    const int dg   = slot & 3;        // d = dg*8 .. +8
    unsigned long long acc[4][4];     // [ii][dpair], f32x2 = (d even, d odd)
    #pragma unroll
    for (int r = 0; r < 4; r++)
        #pragma unroll
        for (int k = 0; k < 4; k++) acc[r][k] = 0ull;

    const float* gh_b = g_h + (size_t)b * N_ * DIN + hh * HD_;

    for (int j0 = 0; j0 < N_; j0 += 128) {
        __syncthreads();
        // stage h tile (coalesced float4)
        #pragma unroll
        for (int r = 0; r < 4; r++) {
            int idx = t + r * 256;
            int j = idx >> 3, d4 = idx & 7;
            *(float4*)&hs[j * 32 + d4 * 4] =
                *(const float4*)&gh_b[(size_t)(j0 + j) * DIN + d4 * 4];
        }
        if (t < 128) ejs[t] = g_ej[(b * N_ + j0 + t) * H_ + hh];
        {   // adj words: [jwl][il], 256 words
            int jwl = t >> 6, il = t & 63;
            adjs[t] = g_adjw[((j0 >> 5) + jwl) * N_ + i0 + il];
        }
        __syncthreads();

        // ---- phase A: 32 scores per thread -> exp-weights into pt[j][i] ----
        {
            const unsigned w = adjs[jq * 64 + iA];
            const float* ej32 = ejs + jq * 32;
            #pragma unroll
            for (int q = 0; q < 8; q++) {
                float4 ev = *(const float4*)&ej32[q * 4];
                float s0 = ei_r + ev.x, s1 = ei_r + ev.y;
                float s2 = ei_r + ev.z, s3 = ei_r + ev.w;
                s0 = fmaxf(s0, 0.2f * s0); s1 = fmaxf(s1, 0.2f * s1);
                s2 = fmaxf(s2, 0.2f * s2); s3 = fmaxf(s3, 0.2f * s3);
                float e0 = ex2f(s0), e1 = ex2f(s1), e2 = ex2f(s2), e3 = ex2f(s3);
                e0 = ((w >> (q*4+0)) & 1u) ? e0 : 0.f;
                e1 = ((w >> (q*4+1)) & 1u) ? e1 : 0.f;
                e2 = ((w >> (q*4+2)) & 1u) ? e2 : 0.f;
                e3 = ((w >> (q*4+3)) & 1u) ? e3 : 0.f;
                const int jb = jq * 32 + q * 4;
                pt[(jb + 0) * 64 + iA] = e0;
                pt[(jb + 1) * 64 + iA] = e1;
                pt[(jb + 2) * 64 + iA] = e2;
                pt[(jb + 3) * 64 + iA] = e3;
                zpart += (e0 + e1) + (e2 + e3);
            }
        }
        __syncthreads();

        // ---- phase B: acc[i,dpair] += P[i,j] * {h[j,d],h[j,d+1]} ----
        #pragma unroll 4
        for (int jj = 0; jj < 32; jj++) {
            const int j = jh * 32 + jj;
            float4 pv = *(const float4*)&pt[j * 64 + ig * 4];
            const float* hrow = &hs[j * 32 + dg * 8];
            ulonglong2 h01 = *(const ulonglong2*)hrow;        // d-pairs 0,1
            ulonglong2 h23 = *(const ulonglong2*)(hrow + 4);  // d-pairs 2,3
            float pf[4] = {pv.x, pv.y, pv.z, pv.w};
            #pragma unroll
            for (int ii = 0; ii < 4; ii++) {
                unsigned long long pp;
                asm("mov.b64 %0, {%1, %1};" : "=l"(pp) : "f"(pf[ii]));
                asm("fma.rn.f32x2 %0, %1, %2, %0;" : "+l"(acc[ii][0]) : "l"(pp), "l"(h01.x));
                asm("fma.rn.f32x2 %0, %1, %2, %0;" : "+l"(acc[ii][1]) : "l"(pp), "l"(h01.y));
                asm("fma.rn.f32x2 %0, %1, %2, %0;" : "+l"(acc[ii][2]) : "l"(pp), "l"(h23.x));
                asm("fma.rn.f32x2 %0, %1, %2, %0;" : "+l"(acc[ii][3]) : "l"(pp), "l"(h23.y));
            }
        }
    }

    // ---- epilogue: spill partials, 4-way jh reduce, normalize, store ----
    __syncthreads();
    zsm[jq * 64 + iA] = zpart;
    float2* buf = (float2*)pt;    // 16 x 256 float2
    #pragma unroll
    for (int ii = 0; ii < 4; ii++)
        #pragma unroll
        for (int dp = 0; dp < 4; dp++)
            buf[(ii * 4 + dp) * 256 + t] = *(float2*)&acc[ii][dp];
    __syncthreads();

    {
        const int i  = t >> 2;        // 0..63
        const int dq = t & 3;         // d block = dq*8
        const int slot_r = (i >> 2) * 4 + dq;
        const int io = i & 3;
        const float zinv = 1.0f / (zsm[i] + zsm[64 + i] + zsm[128 + i] + zsm[192 + i]);
        float o[8];
        #pragma unroll
        for (int dp = 0; dp < 4; dp++) {
            const int k = io * 4 + dp;
            float2 s0 = buf[k * 256 +   0 + slot_r];
            float2 s1 = buf[k * 256 +  64 + slot_r];
            float2 s2 = buf[k * 256 + 128 + slot_r];
            float2 s3 = buf[k * 256 + 192 + slot_r];
            o[2*dp]   = ((s0.x + s1.x) + (s2.x + s3.x)) * zinv;
            o[2*dp+1] = ((s0.y + s1.y) + (s2.y + s3.y)) * zinv;
        }
        float* op = out + ((size_t)(b * N_) + i0 + i) * DIN + hh * HD_ + dq * 8;
        *(float4*)&op[0] = make_float4(o[0], o[1], o[2], o[3]);
        *(float4*)&op[4] = make_float4(o[4], o[5], o[6], o[7]);
    }
}

// ---------------- launch ----------------
extern "C" void kernel_launch(void* const* d_in, const int* in_sizes, int n_in,
                              void* d_out, int out_size) {
    const float* x   = (const float*)d_in[0];
    const int*   adj = (const int*)d_in[1];
    const float* W   = (const float*)d_in[2];
    const float* a   = (const float*)d_in[3];
    float*       out = (float*)d_out;

    cudaFuncSetAttribute(k_gemm, cudaFuncAttributeMaxDynamicSharedMemorySize, GEMM_SMEM);
    cudaFuncSetAttribute(k_attn, cudaFuncAttributeMaxDynamicSharedMemorySize, ATTN_SMEM);

    k_gemm<<<B_ * N_ / 64, 256, GEMM_SMEM>>>(x, W);
    k_eij <<<B_ * N_ / 8, 256>>>(a);
    k_pack<<<(N_ * (N_ / 32) * 32) / 256, 256>>>(adj);
    k_attn<<<dim3(N_ / 64, H_, B_), 256, ATTN_SMEM>>>(out);
}

// round 6
// speedup vs baseline: 1.2589x; 1.2589x over previous
#include <cuda_runtime.h>
#include <cstdint>

#define B_   4
#define N_   2048
#define DIN  128
#define H_   4
#define HD_  32
#define LOG2E 1.4426950408889634f

// ---------------- scratch (no allocs allowed) ----------------
__device__ float    g_h [B_ * N_ * DIN];     // 4 MB
__device__ float    g_ei[B_ * N_ * H_];      // pre-scaled by log2e
__device__ float    g_ej[B_ * N_ * H_];
__device__ unsigned g_adjw[(N_ / 32) * N_];  // [jw][i]  transposed bitmask
// h split f16, transposed per (b,h): [b][h][d][j]
__device__ __align__(16) unsigned short g_hp_hi[B_ * H_ * HD_ * N_];
__device__ __align__(16) unsigned short g_hp_lo[B_ * H_ * HD_ * N_];

__device__ __forceinline__ float ex2f(float x) {
    float r; asm("ex2.approx.ftz.f32 %0, %1;" : "=f"(r) : "f"(x)); return r;
}
// pack (f0 -> low half, f1 -> high half) as f16x2
__device__ __forceinline__ unsigned pk_f16x2(float f0, float f1) {
    unsigned r;
    asm("cvt.rn.f16x2.f32 %0, %1, %2;" : "=r"(r) : "f"(f1), "f"(f0));
    return r;
}
__device__ __forceinline__ void unpk_f16x2(unsigned u, float& f0, float& f1) {
    asm("{ .reg .f16 l, h; mov.b32 {l, h}, %2; cvt.f32.f16 %0, l; cvt.f32.f16 %1, h; }"
        : "=f"(f0), "=f"(f1) : "r"(u));
}
__device__ __forceinline__ unsigned smem_u32(const void* p) {
    unsigned a;
    asm("{ .reg .u64 t; cvta.to.shared.u64 t, %1; cvt.u32.u64 %0, t; }" : "=r"(a) : "l"(p));
    return a;
}

// ---------------- kernel 1: h = x @ W^T (8192x128x128) ----------------
#define WT_STRIDE 132
#define GEMM_SMEM ((128 * WT_STRIDE + 64 * 128) * 4)
__global__ void k_gemm(const float* __restrict__ x, const float* __restrict__ W) {
    extern __shared__ float sm[];
    float* Wt = sm;
    float* xs = sm + 128 * WT_STRIDE;
    const int t = threadIdx.x;
    const int row0 = blockIdx.x * 64;
    for (int idx = t; idx < 128 * 128; idx += 256) {
        int c = idx >> 7, k = idx & 127;
        Wt[k * WT_STRIDE + c] = W[idx];
    }
    for (int idx = t; idx < 64 * 128 / 4; idx += 256)
        *(float4*)&xs[idx * 4] = *(const float4*)&x[(size_t)row0 * 128 + idx * 4];
    __syncthreads();
    const int rg = t >> 5, cg = t & 31;
    float acc[8][4];
    #pragma unroll
    for (int r = 0; r < 8; r++) { acc[r][0]=acc[r][1]=acc[r][2]=acc[r][3]=0.f; }
    #pragma unroll 4
    for (int k = 0; k < 128; k++) {
        float4 wv = *(const float4*)&Wt[k * WT_STRIDE + cg * 4];
        #pragma unroll
        for (int r = 0; r < 8; r++) {
            float xv = xs[(rg * 8 + r) * 128 + k];
            acc[r][0] = fmaf(xv, wv.x, acc[r][0]);
            acc[r][1] = fmaf(xv, wv.y, acc[r][1]);
            acc[r][2] = fmaf(xv, wv.z, acc[r][2]);
            acc[r][3] = fmaf(xv, wv.w, acc[r][3]);
        }
    }
    #pragma unroll
    for (int r = 0; r < 8; r++)
        *(float4*)&g_h[(size_t)(row0 + rg * 8 + r) * 128 + cg * 4] =
            make_float4(acc[r][0], acc[r][1], acc[r][2], acc[r][3]);
}

// ---------------- kernel 1b: ei/ej ----------------
__global__ void k_eij(const float* __restrict__ a) {
    __shared__ float as[256];
    const int t = threadIdx.x;
    if (t < 256) as[t] = a[t] * LOG2E;
    __syncthreads();
    const int warp = t >> 5, lane = t & 31;
    const int row = blockIdx.x * 8 + warp;
    float4 hv = *(const float4*)&g_h[(size_t)row * 128 + lane * 4];
    const int hh = lane >> 3, dbase = (lane & 7) * 4;
    const float* a1 = &as[hh * 64];
    const float* a2 = &as[hh * 64 + 32];
    float p1 = hv.x*a1[dbase]+hv.y*a1[dbase+1]+hv.z*a1[dbase+2]+hv.w*a1[dbase+3];
    float p2 = hv.x*a2[dbase]+hv.y*a2[dbase+1]+hv.z*a2[dbase+2]+hv.w*a2[dbase+3];
    #pragma unroll
    for (int o = 1; o < 8; o <<= 1) {
        p1 += __shfl_xor_sync(0xffffffffu, p1, o, 8);
        p2 += __shfl_xor_sync(0xffffffffu, p2, o, 8);
    }
    if ((lane & 7) == 0) { g_ei[row * H_ + hh] = p1; g_ej[row * H_ + hh] = p2; }
}

// ---------------- kernel 1c: transpose + split h -> f16 hi/lo planes ----------------
__global__ void k_conv() {
    __shared__ float st[32][264];
    const int t = threadIdx.x;
    const int j0 = blockIdx.x * 256, hh = blockIdx.y, b = blockIdx.z;
    const float* src = g_h + (size_t)b * N_ * DIN + hh * HD_;
    #pragma unroll
    for (int r = 0; r < 8; r++) {
        int idx = t + r * 256;              // 2048: j = idx>>3, d4 = idx&7
        int j = idx >> 3, d4 = idx & 7;
        float4 v = *(const float4*)&src[(size_t)(j0 + j) * DIN + d4 * 4];
        st[d4*4+0][j] = v.x; st[d4*4+1][j] = v.y; st[d4*4+2][j] = v.z; st[d4*4+3][j] = v.w;
    }
    __syncthreads();
    const int d = t >> 3, jb = (t & 7) * 32;
    const float* row = &st[d][jb];
    const size_t ob = ((size_t)((b * H_ + hh) * HD_ + d)) * N_ + j0 + jb;
    #pragma unroll
    for (int g = 0; g < 4; g++) {
        unsigned hv[4], lv[4];
        #pragma unroll
        for (int p = 0; p < 4; p++) {
            float f0 = row[g*8 + p*2], f1 = row[g*8 + p*2 + 1];
            unsigned uh = pk_f16x2(f0, f1);
            float g0, g1; unpk_f16x2(uh, g0, g1);
            hv[p] = uh;
            lv[p] = pk_f16x2(f0 - g0, f1 - g1);
        }
        *(uint4*)&g_hp_hi[ob + g*8] = make_uint4(hv[0], hv[1], hv[2], hv[3]);
        *(uint4*)&g_hp_lo[ob + g*8] = make_uint4(lv[0], lv[1], lv[2], lv[3]);
    }
}

// ---------------- kernel 2: pack adj ----------------
__global__ void k_pack(const int* __restrict__ adj) {
    const int gw = (blockIdx.x * blockDim.x + threadIdx.x) >> 5;
    const int lane = threadIdx.x & 31;
    const int i = gw >> 6, jw = gw & 63;
    int v = adj[(size_t)i * N_ + jw * 32 + lane];
    unsigned word = __ballot_sync(0xffffffffu, v != 0);
    if (lane == 0) g_adjw[jw * N_ + i] = word;
}

// ---------------- kernel 3: fused masked softmax + HMMA aggregation ----------------
// grid (32, H, B), 256 threads. BI=64, BJ=128.
// planes: f16, row stride 136 halves = 272 bytes.
#define OFF_PHI 0
#define OFF_PLO 17408
#define OFF_HHI 34816
#define OFF_HLO 43520
#define OFF_EJS 52224
#define OFF_ADJ 52736
#define OFF_ZSM 53760
#define OFF_ZF  54784
#define ATTN_SMEM 55040

__device__ __forceinline__ void ldsm_x4(unsigned addr, unsigned& a0, unsigned& a1,
                                        unsigned& a2, unsigned& a3) {
    asm volatile("ldmatrix.sync.aligned.m8n8.x4.shared.b16 {%0,%1,%2,%3}, [%4];"
                 : "=r"(a0), "=r"(a1), "=r"(a2), "=r"(a3) : "r"(addr));
}
__device__ __forceinline__ void ldsm_x2(unsigned addr, unsigned& b0, unsigned& b1) {
    asm volatile("ldmatrix.sync.aligned.m8n8.x2.shared.b16 {%0,%1}, [%2];"
                 : "=r"(b0), "=r"(b1) : "r"(addr));
}
__device__ __forceinline__ void mma16816(float* d, const unsigned* a, unsigned b0, unsigned b1) {
    asm volatile("mma.sync.aligned.m16n8k16.row.col.f32.f16.f16.f32 "
                 "{%0,%1,%2,%3}, {%4,%5,%6,%7}, {%8,%9}, {%0,%1,%2,%3};"
                 : "+f"(d[0]), "+f"(d[1]), "+f"(d[2]), "+f"(d[3])
                 : "r"(a[0]), "r"(a[1]), "r"(a[2]), "r"(a[3]), "r"(b0), "r"(b1));
}

__global__ void __launch_bounds__(256, 3) k_attn(float* __restrict__ out) {
    extern __shared__ char smc[];
    const unsigned sb = smem_u32(smc);
    float*    ejs  = (float*)(smc + OFF_EJS);
    unsigned* adjs = (unsigned*)(smc + OFF_ADJ);
    float*    zsm  = (float*)(smc + OFF_ZSM);
    float*    zf   = (float*)(smc + OFF_ZF);

    const int t = threadIdx.x, wid = t >> 5, lane = t & 31;
    const int i0 = blockIdx.x * 64, hh = blockIdx.y, b = blockIdx.z;

    // phase-A mapping: iA = t>>2 (64 rows), jq = t&3 (32 j each)
    const int iA = t >> 2, jq = t & 3;
    const float ei_r = g_ei[(b * N_ + i0 + iA) * H_ + hh];
    float zpart = 0.f;

    // phase-B mapping: warp -> (mg, ng)
    const int mg = wid >> 1, ng = wid & 1;
    const int m0 = mg * 16;
    const unsigned aAhi = sb + OFF_PHI + (unsigned)(m0 + (lane & 15)) * 272u + ((lane >> 4) & 1) * 16u;
    const unsigned aAlo = aAhi + (OFF_PLO - OFF_PHI);
    const int bl = lane & 15;
    const unsigned aB0hi = sb + OFF_HHI + (unsigned)(ng * 16 + (bl & 7)) * 272u + ((bl >> 3) & 1) * 16u;
    const unsigned aB1hi = aB0hi + 8u * 272u;
    const unsigned aB0lo = aB0hi + (OFF_HLO - OFF_HHI);
    const unsigned aB1lo = aB1hi + (OFF_HLO - OFF_HHI);

    float d0[4] = {0.f, 0.f, 0.f, 0.f};    // n-tile 0
    float d1[4] = {0.f, 0.f, 0.f, 0.f};    // n-tile 1

    const unsigned short* hp_hi = g_hp_hi + ((size_t)((b * H_ + hh) * HD_)) * N_;
    const unsigned short* hp_lo = g_hp_lo + ((size_t)((b * H_ + hh) * HD_)) * N_;

    for (int tile = 0; tile < 16; tile++) {
        const int j0 = tile * 128;
        __syncthreads();   // previous phase B done with planes

        // ---- stage H planes (f16, [d][j] stride 136h), ejs, adjs ----
        #pragma unroll
        for (int r = 0; r < 4; r++) {
            int id = t + r * 256;               // 0..1023
            int pl = id >> 9, rem = id & 511;
            int d = rem >> 4, q = rem & 15;
            const unsigned short* s = pl ? hp_lo : hp_hi;
            uint4 v = *(const uint4*)&s[(size_t)d * N_ + j0 + q * 8];
            *(uint4*)(smc + (pl ? OFF_HLO : OFF_HHI) + d * 272 + q * 16) = v;
        }
        if (t < 128) ejs[t] = g_ej[(b * N_ + j0 + t) * H_ + hh];
        adjs[t] = g_adjw[((j0 >> 5) + (t >> 6)) * N_ + i0 + (t & 63)];
        __syncthreads();

        // ---- phase A: 32 scores/thread -> f16 hi/lo into P planes ----
        {
            const unsigned w = adjs[jq * 64 + iA];
            const float* ejq = ejs + jq * 32;
            char* phiRow = smc + OFF_PHI + iA * 272 + jq * 64;
            char* ploRow = smc + OFF_PLO + iA * 272 + jq * 64;
            #pragma unroll
            for (int q = 0; q < 8; q++) {
                float4 ev = *(const float4*)&ejq[q * 4];
                float s0 = ei_r + ev.x, s1 = ei_r + ev.y;
                float s2 = ei_r + ev.z, s3 = ei_r + ev.w;
                s0 = fmaxf(s0, 0.2f * s0); s1 = fmaxf(s1, 0.2f * s1);
                s2 = fmaxf(s2, 0.2f * s2); s3 = fmaxf(s3, 0.2f * s3);
                float e0 = ex2f(s0), e1 = ex2f(s1), e2 = ex2f(s2), e3 = ex2f(s3);
                e0 = ((w >> (q*4+0)) & 1u) ? e0 : 0.f;
                e1 = ((w >> (q*4+1)) & 1u) ? e1 : 0.f;
                e2 = ((w >> (q*4+2)) & 1u) ? e2 : 0.f;
                e3 = ((w >> (q*4+3)) & 1u) ? e3 : 0.f;
                zpart += (e0 + e1) + (e2 + e3);
                unsigned uh0 = pk_f16x2(e0, e1), uh1 = pk_f16x2(e2, e3);
                float g0, g1, g2, g3;
                unpk_f16x2(uh0, g0, g1); unpk_f16x2(uh1, g2, g3);
                unsigned ul0 = pk_f16x2(e0 - g0, e1 - g1);
                unsigned ul1 = pk_f16x2(e2 - g2, e3 - g3);
                *(uint2*)(phiRow + q * 8) = make_uint2(uh0, uh1);
                *(uint2*)(ploRow + q * 8) = make_uint2(ul0, ul1);
            }
        }
        __syncthreads();

        // ---- phase B: D += Phi*Hhi + Phi*Hlo + Plo*Hhi (HMMA m16n8k16) ----
        #pragma unroll
        for (int ks = 0; ks < 8; ks++) {
            const unsigned off = (unsigned)ks * 32u;
            unsigned ah[4], al[4], b0h, b1h, b0l, b1l, c0h, c1h, c0l, c1l;
            ldsm_x4(aAhi + off, ah[0], ah[1], ah[2], ah[3]);
            ldsm_x4(aAlo + off, al[0], al[1], al[2], al[3]);
            ldsm_x2(aB0hi + off, b0h, b1h);
            ldsm_x2(aB0lo + off, b0l, b1l);
            ldsm_x2(aB1hi + off, c0h, c1h);
            ldsm_x2(aB1lo + off, c0l, c1l);
            mma16816(d0, ah, b0h, b1h);
            mma16816(d0, ah, b0l, b1l);
            mma16816(d0, al, b0h, b1h);
            mma16816(d1, ah, c0h, c1h);
            mma16816(d1, ah, c0l, c1l);
            mma16816(d1, al, c0h, c1h);
        }
    }

    // ---- epilogue: Z reduce, normalize, store ----
    zsm[jq * 64 + iA] = zpart;
    __syncthreads();
    if (t < 64) zf[t] = 1.0f / (zsm[t] + zsm[64 + t] + zsm[128 + t] + zsm[192 + t]);
    __syncthreads();

    {
        const int gid = lane >> 2, tig = lane & 3;
        const float zi0 = zf[m0 + gid], zi1 = zf[m0 + gid + 8];
        const size_t r0 = (size_t)(b * N_) + i0 + m0 + gid;
        const int colbase = hh * HD_ + ng * 16 + 2 * tig;
        float* o00 = out + r0 * DIN + colbase;
        float* o10 = out + (r0 + 8) * DIN + colbase;
        *(float2*)o00       = make_float2(d0[0] * zi0, d0[1] * zi0);
        *(float2*)(o00 + 8) = make_float2(d1[0] * zi0, d1[1] * zi0);
        *(float2*)o10       = make_float2(d0[2] * zi1, d0[3] * zi1);
        *(float2*)(o10 + 8) = make_float2(d1[2] * zi1, d1[3] * zi1);
    }
}

// ---------------- launch ----------------
extern "C" void kernel_launch(void* const* d_in, const int* in_sizes, int n_in,
                              void* d_out, int out_size) {
    const float* x   = (const float*)d_in[0];
    const int*   adj = (const int*)d_in[1];
    const float* W   = (const float*)d_in[2];
    const float* a   = (const float*)d_in[3];
    float*       out = (float*)d_out;

    cudaFuncSetAttribute(k_gemm, cudaFuncAttributeMaxDynamicSharedMemorySize, GEMM_SMEM);
    cudaFuncSetAttribute(k_attn, cudaFuncAttributeMaxDynamicSharedMemorySize, ATTN_SMEM);

    k_gemm<<<B_ * N_ / 64, 256, GEMM_SMEM>>>(x, W);
    k_eij <<<B_ * N_ / 8, 256>>>(a);
    k_conv<<<dim3(N_ / 256, H_, B_), 256>>>();
    k_pack<<<(N_ * (N_ / 32) * 32) / 256, 256>>>(adj);
    k_attn<<<dim3(N_ / 64, H_, B_), 256, ATTN_SMEM>>>(out);
}

// round 7
// speedup vs baseline: 1.8438x; 1.4646x over previous
#include <cuda_runtime.h>
#include <cstdint>

#define B_   4
#define N_   2048
#define DIN  128
#define H_   4
#define HD_  32
#define LOG2E 1.4426950408889634f

// ---------------- scratch (no allocs allowed) ----------------
__device__ float    g_h [B_ * N_ * DIN];     // 4 MB
__device__ float    g_ei[B_ * N_ * H_];      // pre-scaled by log2e
__device__ float    g_ej[B_ * N_ * H_];
__device__ unsigned g_adjw[(N_ / 32) * N_];  // [jw][i]  transposed bitmask
// h f16, transposed per (b,h): [b][h][d][j]
__device__ __align__(16) unsigned short g_hp[B_ * H_ * HD_ * N_];

__device__ __forceinline__ float ex2f(float x) {
    float r; asm("ex2.approx.ftz.f32 %0, %1;" : "=f"(r) : "f"(x)); return r;
}
__device__ __forceinline__ unsigned pk_f16x2(float f0, float f1) {
    unsigned r;
    asm("cvt.rn.f16x2.f32 %0, %1, %2;" : "=r"(r) : "f"(f1), "f"(f0));
    return r;
}
__device__ __forceinline__ unsigned smem_u32(const void* p) {
    unsigned a;
    asm("{ .reg .u64 t; cvta.to.shared.u64 t, %1; cvt.u32.u64 %0, t; }" : "=r"(a) : "l"(p));
    return a;
}

// ---------------- kernel 1: h = x @ W^T (8192x128x128) ----------------
#define WT_STRIDE 132
#define GEMM_SMEM ((128 * WT_STRIDE + 64 * 128) * 4)
__global__ void k_gemm(const float* __restrict__ x, const float* __restrict__ W) {
    extern __shared__ float sm[];
    float* Wt = sm;
    float* xs = sm + 128 * WT_STRIDE;
    const int t = threadIdx.x;
    const int row0 = blockIdx.x * 64;
    for (int idx = t; idx < 128 * 128; idx += 256) {
        int c = idx >> 7, k = idx & 127;
        Wt[k * WT_STRIDE + c] = W[idx];
    }
    for (int idx = t; idx < 64 * 128 / 4; idx += 256)
        *(float4*)&xs[idx * 4] = *(const float4*)&x[(size_t)row0 * 128 + idx * 4];
    __syncthreads();
    const int rg = t >> 5, cg = t & 31;
    float acc[8][4];
    #pragma unroll
    for (int r = 0; r < 8; r++) { acc[r][0]=acc[r][1]=acc[r][2]=acc[r][3]=0.f; }
    #pragma unroll 4
    for (int k = 0; k < 128; k++) {
        float4 wv = *(const float4*)&Wt[k * WT_STRIDE + cg * 4];
        #pragma unroll
        for (int r = 0; r < 8; r++) {
            float xv = xs[(rg * 8 + r) * 128 + k];
            acc[r][0] = fmaf(xv, wv.x, acc[r][0]);
            acc[r][1] = fmaf(xv, wv.y, acc[r][1]);
            acc[r][2] = fmaf(xv, wv.z, acc[r][2]);
            acc[r][3] = fmaf(xv, wv.w, acc[r][3]);
        }
    }
    #pragma unroll
    for (int r = 0; r < 8; r++)
        *(float4*)&g_h[(size_t)(row0 + rg * 8 + r) * 128 + cg * 4] =
            make_float4(acc[r][0], acc[r][1], acc[r][2], acc[r][3]);
}

// ---------------- kernel 1b: ei/ej ----------------
__global__ void k_eij(const float* __restrict__ a) {
    __shared__ float as[256];
    const int t = threadIdx.x;
    if (t < 256) as[t] = a[t] * LOG2E;
    __syncthreads();
    const int warp = t >> 5, lane = t & 31;
    const int row = blockIdx.x * 8 + warp;
    float4 hv = *(const float4*)&g_h[(size_t)row * 128 + lane * 4];
    const int hh = lane >> 3, dbase = (lane & 7) * 4;
    const float* a1 = &as[hh * 64];
    const float* a2 = &as[hh * 64 + 32];
    float p1 = hv.x*a1[dbase]+hv.y*a1[dbase+1]+hv.z*a1[dbase+2]+hv.w*a1[dbase+3];
    float p2 = hv.x*a2[dbase]+hv.y*a2[dbase+1]+hv.z*a2[dbase+2]+hv.w*a2[dbase+3];
    #pragma unroll
    for (int o = 1; o < 8; o <<= 1) {
        p1 += __shfl_xor_sync(0xffffffffu, p1, o, 8);
        p2 += __shfl_xor_sync(0xffffffffu, p2, o, 8);
    }
    if ((lane & 7) == 0) { g_ei[row * H_ + hh] = p1; g_ej[row * H_ + hh] = p2; }
}

// ---------------- kernel 1c: transpose h -> f16 plane [d][j] ----------------
__global__ void k_conv() {
    __shared__ float st[32][264];
    const int t = threadIdx.x;
    const int j0 = blockIdx.x * 256, hh = blockIdx.y, b = blockIdx.z;
    const float* src = g_h + (size_t)b * N_ * DIN + hh * HD_;
    #pragma unroll
    for (int r = 0; r < 8; r++) {
        int idx = t + r * 256;
        int j = idx >> 3, d4 = idx & 7;
        float4 v = *(const float4*)&src[(size_t)(j0 + j) * DIN + d4 * 4];
        st[d4*4+0][j] = v.x; st[d4*4+1][j] = v.y; st[d4*4+2][j] = v.z; st[d4*4+3][j] = v.w;
    }
    __syncthreads();
    const int d = t >> 3, jb = (t & 7) * 32;
    const float* row = &st[d][jb];
    const size_t ob = ((size_t)((b * H_ + hh) * HD_ + d)) * N_ + j0 + jb;
    #pragma unroll
    for (int g = 0; g < 4; g++) {
        unsigned hv[4];
        #pragma unroll
        for (int p = 0; p < 4; p++)
            hv[p] = pk_f16x2(row[g*8 + p*2], row[g*8 + p*2 + 1]);
        *(uint4*)&g_hp[ob + g*8] = make_uint4(hv[0], hv[1], hv[2], hv[3]);
    }
}

// ---------------- kernel 2: pack adj (vectorized) ----------------
// warp handles 128 j of one row: lane -> sub=lane>>3 (word), idx=lane&7 (int4)
__global__ void k_pack(const int* __restrict__ adj) {
    const int wid = threadIdx.x >> 5, lane = threadIdx.x & 31;
    const int gw = blockIdx.x * 8 + wid;
    const int i = gw >> 4, w4 = gw & 15;
    const int sub = lane >> 3, idx = lane & 7;
    int4 v = *(const int4*)&adj[(size_t)i * N_ + w4 * 128 + sub * 32 + idx * 4];
    unsigned nib = (v.x != 0 ? 1u : 0u) | (v.y != 0 ? 2u : 0u)
                 | (v.z != 0 ? 4u : 0u) | (v.w != 0 ? 8u : 0u);
    unsigned word = nib << (idx * 4);
    word |= __shfl_xor_sync(0xffffffffu, word, 1, 8);
    word |= __shfl_xor_sync(0xffffffffu, word, 2, 8);
    word |= __shfl_xor_sync(0xffffffffu, word, 4, 8);
    if (idx == 0) g_adjw[(w4 * 4 + sub) * N_ + i] = word;
}

// ---------------- kernel 3: fused masked softmax + HMMA (single f16 plane) ----------------
// grid (32, H, B), 256 threads. BI=64, BJ=128. Plane row stride 272B.
#define OFF_PHI  0
#define OFF_HH0  17408
#define OFF_HH1  26112
#define OFF_EJS  34816     // 2 x 512B
#define OFF_ADJ  35840     // 2 x 1024B
#define OFF_ZSM  37888     // 1024B
#define OFF_ZF   38912     // 256B
#define ATTN_SMEM 39168

__device__ __forceinline__ void ldsm_x4(unsigned addr, unsigned& a0, unsigned& a1,
                                        unsigned& a2, unsigned& a3) {
    asm volatile("ldmatrix.sync.aligned.m8n8.x4.shared.b16 {%0,%1,%2,%3}, [%4];"
                 : "=r"(a0), "=r"(a1), "=r"(a2), "=r"(a3) : "r"(addr));
}
__device__ __forceinline__ void mma16816(float* d, const unsigned* a, unsigned b0, unsigned b1) {
    asm volatile("mma.sync.aligned.m16n8k16.row.col.f32.f16.f16.f32 "
                 "{%0,%1,%2,%3}, {%4,%5,%6,%7}, {%8,%9}, {%0,%1,%2,%3};"
                 : "+f"(d[0]), "+f"(d[1]), "+f"(d[2]), "+f"(d[3])
                 : "r"(a[0]), "r"(a[1]), "r"(a[2]), "r"(a[3]), "r"(b0), "r"(b1));
}

__global__ void __launch_bounds__(256, 5) k_attn(float* __restrict__ out) {
    extern __shared__ char smc[];
    const unsigned sb = smem_u32(smc);
    float*    zsm = (float*)(smc + OFF_ZSM);
    float*    zf  = (float*)(smc + OFF_ZF);

    const int t = threadIdx.x, wid = t >> 5, lane = t & 31;
    const int i0 = blockIdx.x * 64, hh = blockIdx.y, b = blockIdx.z;

    // phase-A mapping
    const int iA = t >> 2, jq = t & 3;
    const float ei_r = g_ei[(b * N_ + i0 + iA) * H_ + hh];
    float zpart = 0.f;

    // phase-B mapping
    const int mg = wid >> 1, ng = wid & 1;
    const int m0 = mg * 16;
    const unsigned aA = sb + OFF_PHI + (unsigned)(m0 + (lane & 15)) * 272u
                      + ((lane >> 4) & 1) * 16u;
    const unsigned bRow = (unsigned)(ng * 16 + (lane & 7) + ((lane >> 4) & 1) * 8) * 272u
                        + ((lane >> 3) & 1) * 16u;
    const unsigned aB0 = sb + OFF_HH0 + bRow;
    const unsigned aB1 = sb + OFF_HH1 + bRow;

    float d0[4] = {0.f, 0.f, 0.f, 0.f};
    float d1[4] = {0.f, 0.f, 0.f, 0.f};

    const unsigned short* hp = g_hp + ((size_t)((b * H_ + hh) * HD_)) * N_;

    // ---- stage helper (inlined twice) ----
    #define STAGE(buf, jj0)                                                          \
    do {                                                                             \
        _Pragma("unroll")                                                            \
        for (int r = 0; r < 2; r++) {                                                \
            int id = t + r * 256;                                                    \
            int d = id >> 4, q = id & 15;                                            \
            uint4 v = *(const uint4*)&hp[(size_t)d * N_ + (jj0) + q * 8];            \
            *(uint4*)(smc + ((buf) ? OFF_HH1 : OFF_HH0) + d * 272 + q * 16) = v;     \
        }                                                                            \
        if (t < 128)                                                                 \
            *(float*)(smc + OFF_EJS + (buf) * 512 + t * 4) =                         \
                g_ej[(b * N_ + (jj0) + t) * H_ + hh];                                \
        *(unsigned*)(smc + OFF_ADJ + (buf) * 1024 + t * 4) =                         \
            g_adjw[(((jj0) >> 5) + (t >> 6)) * N_ + i0 + (t & 63)];                  \
    } while (0)

    STAGE(0, 0);

    for (int tile = 0; tile < 16; tile++) {
        const int cur = tile & 1;
        __syncthreads();   // stage(cur) visible; P free (prev phase B done)

        // prefetch next tile first (LDG latency overlaps phase A)
        if (tile < 15) STAGE(cur ^ 1, (tile + 1) * 128);

        // ---- phase A: 32 scores/thread -> f16 into P plane ----
        {
            const unsigned w = *(const unsigned*)(smc + OFF_ADJ + cur * 1024 + (jq * 64 + iA) * 4);
            const float* ejq = (const float*)(smc + OFF_EJS + cur * 512) + jq * 32;
            char* phiRow = smc + OFF_PHI + iA * 272 + jq * 64;
            #pragma unroll
            for (int q = 0; q < 8; q++) {
                float4 ev = *(const float4*)&ejq[q * 4];
                float s0 = ei_r + ev.x, s1 = ei_r + ev.y;
                float s2 = ei_r + ev.z, s3 = ei_r + ev.w;
                s0 = fmaxf(s0, 0.2f * s0); s1 = fmaxf(s1, 0.2f * s1);
                s2 = fmaxf(s2, 0.2f * s2); s3 = fmaxf(s3, 0.2f * s3);
                float e0 = ex2f(s0), e1 = ex2f(s1), e2 = ex2f(s2), e3 = ex2f(s3);
                e0 = ((w >> (q*4+0)) & 1u) ? e0 : 0.f;
                e1 = ((w >> (q*4+1)) & 1u) ? e1 : 0.f;
                e2 = ((w >> (q*4+2)) & 1u) ? e2 : 0.f;
                e3 = ((w >> (q*4+3)) & 1u) ? e3 : 0.f;
                zpart += (e0 + e1) + (e2 + e3);
                *(uint2*)(phiRow + q * 8) = make_uint2(pk_f16x2(e0, e1), pk_f16x2(e2, e3));
            }
        }
        __syncthreads();   // P ready; H(cur) ready

        // ---- phase B: D += P * H  (2 ldsm.x4 + 2 HMMA per k-step) ----
        const unsigned aB = cur ? aB1 : aB0;
        #pragma unroll
        for (int ks = 0; ks < 8; ks++) {
            const unsigned off = (unsigned)ks * 32u;
            unsigned a[4], b0, b1, c0, c1;
            ldsm_x4(aA + off, a[0], a[1], a[2], a[3]);
            ldsm_x4(aB + off, b0, b1, c0, c1);
            mma16816(d0, a, b0, b1);
            mma16816(d1, a, c0, c1);
        }
    }

    // ---- epilogue: Z reduce, normalize, store ----
    zsm[jq * 64 + iA] = zpart;
    __syncthreads();
    if (t < 64) zf[t] = 1.0f / (zsm[t] + zsm[64 + t] + zsm[128 + t] + zsm[192 + t]);
    __syncthreads();

    {
        const int gid = lane >> 2, tig = lane & 3;
        const float zi0 = zf[m0 + gid], zi1 = zf[m0 + gid + 8];
        const size_t r0 = (size_t)(b * N_) + i0 + m0 + gid;
        const int colbase = hh * HD_ + ng * 16 + 2 * tig;
        float* o00 = out + r0 * DIN + colbase;
        float* o10 = out + (r0 + 8) * DIN + colbase;
        *(float2*)o00       = make_float2(d0[0] * zi0, d0[1] * zi0);
        *(float2*)(o00 + 8) = make_float2(d1[0] * zi0, d1[1] * zi0);
        *(float2*)o10       = make_float2(d0[2] * zi1, d0[3] * zi1);
        *(float2*)(o10 + 8) = make_float2(d1[2] * zi1, d1[3] * zi1);
    }
}

// ---------------- launch ----------------
extern "C" void kernel_launch(void* const* d_in, const int* in_sizes, int n_in,
                              void* d_out, int out_size) {
    const float* x   = (const float*)d_in[0];
    const int*   adj = (const int*)d_in[1];
    const float* W   = (const float*)d_in[2];
    const float* a   = (const float*)d_in[3];
    float*       out = (float*)d_out;

    cudaFuncSetAttribute(k_gemm, cudaFuncAttributeMaxDynamicSharedMemorySize, GEMM_SMEM);
    cudaFuncSetAttribute(k_attn, cudaFuncAttributeMaxDynamicSharedMemorySize, ATTN_SMEM);

    k_gemm<<<B_ * N_ / 64, 256, GEMM_SMEM>>>(x, W);
    k_eij <<<B_ * N_ / 8, 256>>>(a);
    k_conv<<<dim3(N_ / 256, H_, B_), 256>>>();
    k_pack<<<N_ * 16 / 8, 256>>>(adj);
    k_attn<<<dim3(N_ / 64, H_, B_), 256, ATTN_SMEM>>>(out);
}

// round 8
// speedup vs baseline: 2.4710x; 1.3401x over previous
#include <cuda_runtime.h>
#include <cstdint>

#define B_   4
#define N_   2048
#define DIN  128
#define H_   4
#define HD_  32
#define LOG2E 1.4426950408889634f

// ---------------- scratch (no allocs allowed) ----------------
__device__ float    g_h [B_ * N_ * DIN];     // 4 MB
__device__ float    g_ei[B_ * N_ * H_];      // pre-scaled by log2e
__device__ float    g_ej[B_ * N_ * H_];
__device__ unsigned g_adjw[(N_ / 32) * N_];  // [jw][i]  transposed bitmask
// h f16, transposed per (b,h): [b][h][d][j]
__device__ __align__(16) unsigned short g_hp[B_ * H_ * HD_ * N_];

__device__ __forceinline__ float ex2f(float x) {
    float r; asm("ex2.approx.ftz.f32 %0, %1;" : "=f"(r) : "f"(x)); return r;
}
__device__ __forceinline__ unsigned pk_f16x2(float f0, float f1) {
    unsigned r;
    asm("cvt.rn.f16x2.f32 %0, %1, %2;" : "=r"(r) : "f"(f1), "f"(f0));
    return r;
}
__device__ __forceinline__ unsigned smem_u32(const void* p) {
    unsigned a;
    asm("{ .reg .u64 t; cvta.to.shared.u64 t, %1; cvt.u32.u64 %0, t; }" : "=r"(a) : "l"(p));
    return a;
}

// ---------------- kernel 1: h = x @ W^T (8192x128x128) ----------------
#define WT_STRIDE 132
#define GEMM_SMEM ((128 * WT_STRIDE + 64 * 128) * 4)
__global__ void k_gemm(const float* __restrict__ x, const float* __restrict__ W) {
    extern __shared__ float sm[];
    float* Wt = sm;
    float* xs = sm + 128 * WT_STRIDE;
    const int t = threadIdx.x;
    const int row0 = blockIdx.x * 64;
    for (int idx = t; idx < 128 * 128; idx += 256) {
        int c = idx >> 7, k = idx & 127;
        Wt[k * WT_STRIDE + c] = W[idx];
    }
    for (int idx = t; idx < 64 * 128 / 4; idx += 256)
        *(float4*)&xs[idx * 4] = *(const float4*)&x[(size_t)row0 * 128 + idx * 4];
    __syncthreads();
    const int rg = t >> 5, cg = t & 31;
    float acc[8][4];
    #pragma unroll
    for (int r = 0; r < 8; r++) { acc[r][0]=acc[r][1]=acc[r][2]=acc[r][3]=0.f; }
    #pragma unroll 4
    for (int k = 0; k < 128; k++) {
        float4 wv = *(const float4*)&Wt[k * WT_STRIDE + cg * 4];
        #pragma unroll
        for (int r = 0; r < 8; r++) {
            float xv = xs[(rg * 8 + r) * 128 + k];
            acc[r][0] = fmaf(xv, wv.x, acc[r][0]);
            acc[r][1] = fmaf(xv, wv.y, acc[r][1]);
            acc[r][2] = fmaf(xv, wv.z, acc[r][2]);
            acc[r][3] = fmaf(xv, wv.w, acc[r][3]);
        }
    }
    #pragma unroll
    for (int r = 0; r < 8; r++)
        *(float4*)&g_h[(size_t)(row0 + rg * 8 + r) * 128 + cg * 4] =
            make_float4(acc[r][0], acc[r][1], acc[r][2], acc[r][3]);
}

// ---------------- kernel 1b: ei/ej ----------------
__global__ void k_eij(const float* __restrict__ a) {
    __shared__ float as[256];
    const int t = threadIdx.x;
    if (t < 256) as[t] = a[t] * LOG2E;
    __syncthreads();
    const int warp = t >> 5, lane = t & 31;
    const int row = blockIdx.x * 8 + warp;
    float4 hv = *(const float4*)&g_h[(size_t)row * 128 + lane * 4];
    const int hh = lane >> 3, dbase = (lane & 7) * 4;
    const float* a1 = &as[hh * 64];
    const float* a2 = &as[hh * 64 + 32];
    float p1 = hv.x*a1[dbase]+hv.y*a1[dbase+1]+hv.z*a1[dbase+2]+hv.w*a1[dbase+3];
    float p2 = hv.x*a2[dbase]+hv.y*a2[dbase+1]+hv.z*a2[dbase+2]+hv.w*a2[dbase+3];
    #pragma unroll
    for (int o = 1; o < 8; o <<= 1) {
        p1 += __shfl_xor_sync(0xffffffffu, p1, o, 8);
        p2 += __shfl_xor_sync(0xffffffffu, p2, o, 8);
    }
    if ((lane & 7) == 0) { g_ei[row * H_ + hh] = p1; g_ej[row * H_ + hh] = p2; }
}

// ---------------- kernel 1c: transpose h -> f16 plane [d][j] ----------------
__global__ void k_conv() {
    __shared__ float st[32][264];
    const int t = threadIdx.x;
    const int j0 = blockIdx.x * 256, hh = blockIdx.y, b = blockIdx.z;
    const float* src = g_h + (size_t)b * N_ * DIN + hh * HD_;
    #pragma unroll
    for (int r = 0; r < 8; r++) {
        int idx = t + r * 256;
        int j = idx >> 3, d4 = idx & 7;
        float4 v = *(const float4*)&src[(size_t)(j0 + j) * DIN + d4 * 4];
        st[d4*4+0][j] = v.x; st[d4*4+1][j] = v.y; st[d4*4+2][j] = v.z; st[d4*4+3][j] = v.w;
    }
    __syncthreads();
    const int d = t >> 3, jb = (t & 7) * 32;
    const float* row = &st[d][jb];
    const size_t ob = ((size_t)((b * H_ + hh) * HD_ + d)) * N_ + j0 + jb;
    #pragma unroll
    for (int g = 0; g < 4; g++) {
        unsigned hv[4];
        #pragma unroll
        for (int p = 0; p < 4; p++)
            hv[p] = pk_f16x2(row[g*8 + p*2], row[g*8 + p*2 + 1]);
        *(uint4*)&g_hp[ob + g*8] = make_uint4(hv[0], hv[1], hv[2], hv[3]);
    }
}

// ---------------- kernel 2: pack adj (vectorized, 2 rows/warp) ----------------
__global__ void k_pack(const int* __restrict__ adj) {
    const int wid = threadIdx.x >> 5, lane = threadIdx.x & 31;
    const int gw = blockIdx.x * 8 + wid;           // 16384 warps
    const int ip = gw >> 4, w4 = gw & 15;          // rows 2ip, 2ip+1
    const int sub = lane >> 3, idx = lane & 7;
    const size_t base = (size_t)(2 * ip) * N_ + w4 * 128 + sub * 32 + idx * 4;
    int4 v0 = *(const int4*)&adj[base];
    int4 v1 = *(const int4*)&adj[base + N_];
    unsigned a0 = ((v0.x != 0 ? 1u : 0u) | (v0.y != 0 ? 2u : 0u)
                 | (v0.z != 0 ? 4u : 0u) | (v0.w != 0 ? 8u : 0u)) << (idx * 4);
    unsigned a1 = ((v1.x != 0 ? 1u : 0u) | (v1.y != 0 ? 2u : 0u)
                 | (v1.z != 0 ? 4u : 0u) | (v1.w != 0 ? 8u : 0u)) << (idx * 4);
    #pragma unroll
    for (int o = 1; o < 8; o <<= 1) {
        a0 |= __shfl_xor_sync(0xffffffffu, a0, o, 8);
        a1 |= __shfl_xor_sync(0xffffffffu, a1, o, 8);
    }
    if (idx == 0) {
        g_adjw[(w4 * 4 + sub) * N_ + 2 * ip]     = a0;
        g_adjw[(w4 * 4 + sub) * N_ + 2 * ip + 1] = a1;
    }
}

// ---------------- kernel 3: warp-specialized softmax + HMMA ----------------
// 256 thr: warps 0-3 producers (scores->P), warps 4-7 consumers (HMMA).
// BI=64, BJ=128. P/H/ej/adj double-buffered, mbarrier handoff.
#define OFF_P0   0
#define OFF_P1   17408
#define OFF_H0   34816
#define OFF_H1   43520
#define OFF_EJ   52224     // 2 x 512B
#define OFF_ADJ  53248     // 2 x 1024B
#define OFF_ZSM  55296     // 512B
#define OFF_ZF   55808     // 256B
#define OFF_MBAR 56064     // 4 x 8B: pfull0, pfull1, pempty0, pempty1
#define ATTN_SMEM 56192

__device__ __forceinline__ void ldsm_x4(unsigned addr, unsigned& a0, unsigned& a1,
                                        unsigned& a2, unsigned& a3) {
    asm volatile("ldmatrix.sync.aligned.m8n8.x4.shared.b16 {%0,%1,%2,%3}, [%4];"
                 : "=r"(a0), "=r"(a1), "=r"(a2), "=r"(a3) : "r"(addr));
}
__device__ __forceinline__ void mma16816(float* d, const unsigned* a, unsigned b0, unsigned b1) {
    asm volatile("mma.sync.aligned.m16n8k16.row.col.f32.f16.f16.f32 "
                 "{%0,%1,%2,%3}, {%4,%5,%6,%7}, {%8,%9}, {%0,%1,%2,%3};"
                 : "+f"(d[0]), "+f"(d[1]), "+f"(d[2]), "+f"(d[3])
                 : "r"(a[0]), "r"(a[1]), "r"(a[2]), "r"(a[3]), "r"(b0), "r"(b1));
}
__device__ __forceinline__ void mbar_wait(unsigned mb, unsigned parity) {
    asm volatile(
        "{\n\t.reg .pred P1;\n\t"
        "WL_%=:\n\t"
        "mbarrier.try_wait.parity.acquire.cta.shared::cta.b64 P1, [%0], %1, 0x989680;\n\t"
        "@P1 bra.uni WD_%=;\n\t"
        "bra.uni WL_%=;\n\t"
        "WD_%=:\n\t}"
        :: "r"(mb), "r"(parity) : "memory");
}
__device__ __forceinline__ void mbar_arrive(unsigned mb) {
    asm volatile("mbarrier.arrive.shared.b64 _, [%0];" :: "r"(mb) : "memory");
}

__global__ void __launch_bounds__(256, 4) k_attn(float* __restrict__ out) {
    extern __shared__ char smc[];
    const unsigned sb = smem_u32(smc);
    float* zsm = (float*)(smc + OFF_ZSM);
    float* zf  = (float*)(smc + OFF_ZF);

    const int t = threadIdx.x, wid = t >> 5, lane = t & 31;
    const int i0 = blockIdx.x * 64, hh = blockIdx.y, b = blockIdx.z;

    const unsigned mb_pfull0  = sb + OFF_MBAR;
    const unsigned mb_pfull1  = sb + OFF_MBAR + 8;
    const unsigned mb_pempty0 = sb + OFF_MBAR + 16;
    const unsigned mb_pempty1 = sb + OFF_MBAR + 24;

    if (t == 0) {
        asm volatile("mbarrier.init.shared.b64 [%0], %1;" :: "r"(mb_pfull0),  "r"(128u) : "memory");
        asm volatile("mbarrier.init.shared.b64 [%0], %1;" :: "r"(mb_pfull1),  "r"(128u) : "memory");
        asm volatile("mbarrier.init.shared.b64 [%0], %1;" :: "r"(mb_pempty0), "r"(128u) : "memory");
        asm volatile("mbarrier.init.shared.b64 [%0], %1;" :: "r"(mb_pempty1), "r"(128u) : "memory");
    }
    __syncthreads();

    if (wid < 4) {
        // ================= PRODUCERS (t in [0,128)) =================
        const int iA = t >> 1, jq2 = t & 1;        // 64 rows x 2 j-halves
        const float ei_r = g_ei[(b * N_ + i0 + iA) * H_ + hh];
        float zpart = 0.f;
        const unsigned short* hp = g_hp + ((size_t)((b * H_ + hh) * HD_)) * N_;

        for (int tile = 0; tile < 16; tile++) {
            const int cur = tile & 1;
            const int j0 = tile * 128;
            const unsigned offH = cur ? OFF_H1 : OFF_H0;
            const unsigned offP = cur ? OFF_P1 : OFF_P0;

            if (tile >= 2)
                mbar_wait(cur ? mb_pempty1 : mb_pempty0, (unsigned)(((tile >> 1) - 1) & 1));

            // stage H (512 uint4), ej (128 f32), adj (256 u32)
            #pragma unroll
            for (int r = 0; r < 4; r++) {
                int id = t + r * 128;
                int d = id >> 4, q = id & 15;
                uint4 v = *(const uint4*)&hp[(size_t)d * N_ + j0 + q * 8];
                *(uint4*)(smc + offH + d * 272 + q * 16) = v;
            }
            *(float*)(smc + OFF_EJ + cur * 512 + t * 4) = g_ej[(b * N_ + j0 + t) * H_ + hh];
            #pragma unroll
            for (int r = 0; r < 2; r++) {
                int id = t + r * 128;
                *(unsigned*)(smc + OFF_ADJ + cur * 1024 + id * 4) =
                    g_adjw[((j0 >> 5) + (id >> 6)) * N_ + i0 + (id & 63)];
            }
            asm volatile("bar.sync 1, 128;" ::: "memory");

            // scores: 64 j per thread
            {
                const unsigned* aw = (const unsigned*)(smc + OFF_ADJ + cur * 1024);
                const unsigned w0 = aw[(jq2 * 2 + 0) * 64 + iA];
                const unsigned w1 = aw[(jq2 * 2 + 1) * 64 + iA];
                const float* ejq = (const float*)(smc + OFF_EJ + cur * 512) + jq2 * 64;
                char* phiRow = smc + offP + iA * 272 + jq2 * 128;
                #pragma unroll 8
                for (int q = 0; q < 16; q++) {
                    const unsigned w = (q < 8) ? w0 : w1;
                    const int bit = (q & 7) * 4;
                    float4 ev = *(const float4*)&ejq[q * 4];
                    float s0 = ei_r + ev.x, s1 = ei_r + ev.y;
                    float s2 = ei_r + ev.z, s3 = ei_r + ev.w;
                    s0 = fmaxf(s0, 0.2f * s0); s1 = fmaxf(s1, 0.2f * s1);
                    s2 = fmaxf(s2, 0.2f * s2); s3 = fmaxf(s3, 0.2f * s3);
                    float e0 = ex2f(s0), e1 = ex2f(s1), e2 = ex2f(s2), e3 = ex2f(s3);
                    e0 = ((w >> (bit + 0)) & 1u) ? e0 : 0.f;
                    e1 = ((w >> (bit + 1)) & 1u) ? e1 : 0.f;
                    e2 = ((w >> (bit + 2)) & 1u) ? e2 : 0.f;
                    e3 = ((w >> (bit + 3)) & 1u) ? e3 : 0.f;
                    zpart += (e0 + e1) + (e2 + e3);
                    *(uint2*)(phiRow + q * 8) = make_uint2(pk_f16x2(e0, e1), pk_f16x2(e2, e3));
                }
            }
            mbar_arrive(cur ? mb_pfull1 : mb_pfull0);
        }

        zsm[jq2 * 64 + iA] = zpart;
        asm volatile("bar.sync 1, 128;" ::: "memory");
        if (t < 64) zf[t] = 1.0f / (zsm[t] + zsm[64 + t]);
        __syncthreads();       // join with consumers
    } else {
        // ================= CONSUMERS (warps 4-7) =================
        const int w = wid - 4;                      // m strip = w*16
        const unsigned aAr = (unsigned)(w * 16 + (lane & 15)) * 272u + ((lane >> 4) & 1) * 16u;
        const unsigned bRow = (unsigned)((lane & 7) + ((lane >> 4) & 1) * 8) * 272u
                            + ((lane >> 3) & 1) * 16u;
        float dacc[4][4];
        #pragma unroll
        for (int nb = 0; nb < 4; nb++)
            #pragma unroll
            for (int k = 0; k < 4; k++) dacc[nb][k] = 0.f;

        for (int tile = 0; tile < 16; tile++) {
            const int cur = tile & 1;
            mbar_wait(cur ? mb_pfull1 : mb_pfull0, (unsigned)((tile >> 1) & 1));
            const unsigned aA  = sb + (cur ? OFF_P1 : OFF_P0) + aAr;
            const unsigned aB0 = sb + (cur ? OFF_H1 : OFF_H0) + bRow;
            const unsigned aB1 = aB0 + 16u * 272u;
            #pragma unroll
            for (int ks = 0; ks < 8; ks++) {
                const unsigned off = (unsigned)ks * 32u;
                unsigned a[4], b0, b1, c0, c1, e0, e1, f0, f1;
                ldsm_x4(aA + off, a[0], a[1], a[2], a[3]);
                ldsm_x4(aB0 + off, b0, b1, c0, c1);
                ldsm_x4(aB1 + off, e0, e1, f0, f1);
                mma16816(dacc[0], a, b0, b1);
                mma16816(dacc[1], a, c0, c1);
                mma16816(dacc[2], a, e0, e1);
                mma16816(dacc[3], a, f0, f1);
            }
            mbar_arrive(cur ? mb_pempty1 : mb_pempty0);
        }

        __syncthreads();       // join: zf ready

        const int gid = lane >> 2, tig = lane & 3;
        const float zi0 = zf[w * 16 + gid], zi1 = zf[w * 16 + gid + 8];
        const size_t r0 = (size_t)(b * N_) + i0 + w * 16 + gid;
        float* o0 = out + r0 * DIN + hh * HD_ + 2 * tig;
        float* o1 = o0 + 8 * DIN;
        #pragma unroll
        for (int nb = 0; nb < 4; nb++) {
            *(float2*)(o0 + nb * 8) = make_float2(dacc[nb][0] * zi0, dacc[nb][1] * zi0);
            *(float2*)(o1 + nb * 8) = make_float2(dacc[nb][2] * zi1, dacc[nb][3] * zi1);
        }
    }
}

// ---------------- launch ----------------
extern "C" void kernel_launch(void* const* d_in, const int* in_sizes, int n_in,
                              void* d_out, int out_size) {
    const float* x   = (const float*)d_in[0];
    const int*   adj = (const int*)d_in[1];
    const float* W   = (const float*)d_in[2];
    const float* a   = (const float*)d_in[3];
    float*       out = (float*)d_out;

    cudaFuncSetAttribute(k_gemm, cudaFuncAttributeMaxDynamicSharedMemorySize, GEMM_SMEM);
    cudaFuncSetAttribute(k_attn, cudaFuncAttributeMaxDynamicSharedMemorySize, ATTN_SMEM);

    k_gemm<<<B_ * N_ / 64, 256, GEMM_SMEM>>>(x, W);
    k_eij <<<B_ * N_ / 8, 256>>>(a);
    k_conv<<<dim3(N_ / 256, H_, B_), 256>>>();
    k_pack<<<2048, 256>>>(adj);
    k_attn<<<dim3(N_ / 64, H_, B_), 256, ATTN_SMEM>>>(out);
}

// round 9
// speedup vs baseline: 2.8796x; 1.1654x over previous
#include <cuda_runtime.h>
#include <cuda_fp16.h>
#include <cstdint>

#define B_   4
#define N_   2048
#define DIN  128
#define H_   4
#define HD_  32
#define LOG2E 1.4426950408889634f

// ---------------- scratch (no allocs allowed) ----------------
__device__ float    g_h [B_ * N_ * DIN];     // 4 MB
__device__ float    g_ei[B_ * N_ * H_];      // pre-scaled by log2e
__device__ float    g_ej[B_ * N_ * H_];
__device__ unsigned g_adjw[(N_ / 32) * N_];  // [jw][i]  transposed bitmask
// h f16, transposed per (b,h): [b][h][d][j]
__device__ __align__(16) unsigned short g_hp[B_ * H_ * HD_ * N_];

__device__ __forceinline__ float ex2f(float x) {
    float r; asm("ex2.approx.ftz.f32 %0, %1;" : "=f"(r) : "f"(x)); return r;
}
__device__ __forceinline__ unsigned pk_f16x2(float f0, float f1) {
    unsigned r;
    asm("cvt.rn.f16x2.f32 %0, %1, %2;" : "=r"(r) : "f"(f1), "f"(f0));
    return r;
}
__device__ __forceinline__ unsigned smem_u32(const void* p) {
    unsigned a;
    asm("{ .reg .u64 t; cvta.to.shared.u64 t, %1; cvt.u32.u64 %0, t; }" : "=r"(a) : "l"(p));
    return a;
}
#define CP16(dst, src) asm volatile("cp.async.cg.shared.global [%0], [%1], 16;" :: "r"(dst), "l"(src) : "memory")
#define CP4(dst, src)  asm volatile("cp.async.ca.shared.global [%0], [%1], 4;"  :: "r"(dst), "l"(src) : "memory")

// ---------------- kernel 1: h = x @ W^T + fused f16 transpose epilogue ----------------
#define WT_STRIDE 132
#define GEMM_SMEM ((128 * WT_STRIDE + 64 * 128) * 4)
__global__ void k_gemm(const float* __restrict__ x, const float* __restrict__ W) {
    extern __shared__ float sm[];
    float* Wt = sm;
    float* xs = sm + 128 * WT_STRIDE;
    const int t = threadIdx.x;
    const int row0 = blockIdx.x * 64;
    for (int idx = t; idx < 128 * 128; idx += 256) {
        int c = idx >> 7, k = idx & 127;
        Wt[k * WT_STRIDE + c] = W[idx];
    }
    for (int idx = t; idx < 64 * 128 / 4; idx += 256)
        *(float4*)&xs[idx * 4] = *(const float4*)&x[(size_t)row0 * 128 + idx * 4];
    __syncthreads();
    const int rg = t >> 5, cg = t & 31;
    float acc[8][4];
    #pragma unroll
    for (int r = 0; r < 8; r++) { acc[r][0]=acc[r][1]=acc[r][2]=acc[r][3]=0.f; }
    #pragma unroll 4
    for (int k = 0; k < 128; k++) {
        float4 wv = *(const float4*)&Wt[k * WT_STRIDE + cg * 4];
        #pragma unroll
        for (int r = 0; r < 8; r++) {
            float xv = xs[(rg * 8 + r) * 128 + k];
            acc[r][0] = fmaf(xv, wv.x, acc[r][0]);
            acc[r][1] = fmaf(xv, wv.y, acc[r][1]);
            acc[r][2] = fmaf(xv, wv.z, acc[r][2]);
            acc[r][3] = fmaf(xv, wv.w, acc[r][3]);
        }
    }
    #pragma unroll
    for (int r = 0; r < 8; r++)
        *(float4*)&g_h[(size_t)(row0 + rg * 8 + r) * 128 + cg * 4] =
            make_float4(acc[r][0], acc[r][1], acc[r][2], acc[r][3]);

    // epilogue: transpose to f16 plane [d][j] via smem (replaces k_conv)
    __syncthreads();
    unsigned short* sm16 = (unsigned short*)sm;    // [128 d][72]
    #pragma unroll
    for (int r = 0; r < 8; r++) {
        const int jl = rg * 8 + r;
        #pragma unroll
        for (int c = 0; c < 4; c++)
            sm16[(cg * 4 + c) * 72 + jl] = __half_as_ushort(__float2half_rn(acc[r][c]));
    }
    __syncthreads();
    {
        const int bb = row0 >> 11, j0l = row0 & 2047;
        #pragma unroll
        for (int p = 0; p < 4; p++) {
            int idx = t + p * 256;              // 0..1023
            int d = idx >> 3, q = idx & 7;
            uint4 v = *(uint4*)&sm16[d * 72 + q * 8];
            int hh2 = d >> 5, dd = d & 31;
            *(uint4*)&g_hp[(((size_t)bb * H_ + hh2) * HD_ + dd) * N_ + j0l + q * 8] = v;
        }
    }
}

// ---------------- kernel 1b: ei/ej ----------------
__global__ void k_eij(const float* __restrict__ a) {
    __shared__ float as[256];
    const int t = threadIdx.x;
    if (t < 256) as[t] = a[t] * LOG2E;
    __syncthreads();
    const int warp = t >> 5, lane = t & 31;
    const int row = blockIdx.x * 8 + warp;
    float4 hv = *(const float4*)&g_h[(size_t)row * 128 + lane * 4];
    const int hh = lane >> 3, dbase = (lane & 7) * 4;
    const float* a1 = &as[hh * 64];
    const float* a2 = &as[hh * 64 + 32];
    float p1 = hv.x*a1[dbase]+hv.y*a1[dbase+1]+hv.z*a1[dbase+2]+hv.w*a1[dbase+3];
    float p2 = hv.x*a2[dbase]+hv.y*a2[dbase+1]+hv.z*a2[dbase+2]+hv.w*a2[dbase+3];
    #pragma unroll
    for (int o = 1; o < 8; o <<= 1) {
        p1 += __shfl_xor_sync(0xffffffffu, p1, o, 8);
        p2 += __shfl_xor_sync(0xffffffffu, p2, o, 8);
    }
    if ((lane & 7) == 0) { g_ei[row * H_ + hh] = p1; g_ej[row * H_ + hh] = p2; }
}

// ---------------- kernel 2: pack adj (4 rows/warp, uint4 out) ----------------
__global__ void k_pack(const int* __restrict__ adj) {
    const int wid = threadIdx.x >> 5, lane = threadIdx.x & 31;
    const int gw = blockIdx.x * 8 + wid;           // 8192 warps
    const int ip = gw >> 4, w4 = gw & 15;          // rows 4ip..4ip+3
    const int sub = lane >> 3, idx = lane & 7;
    const size_t base = (size_t)(4 * ip) * N_ + w4 * 128 + sub * 32 + idx * 4;
    unsigned aa[4];
    #pragma unroll
    for (int k = 0; k < 4; k++) {
        int4 v = *(const int4*)&adj[base + (size_t)k * N_];
        aa[k] = ((v.x != 0 ? 1u : 0u) | (v.y != 0 ? 2u : 0u)
               | (v.z != 0 ? 4u : 0u) | (v.w != 0 ? 8u : 0u)) << (idx * 4);
    }
    #pragma unroll
    for (int o = 1; o < 8; o <<= 1) {
        aa[0] |= __shfl_xor_sync(0xffffffffu, aa[0], o, 8);
        aa[1] |= __shfl_xor_sync(0xffffffffu, aa[1], o, 8);
        aa[2] |= __shfl_xor_sync(0xffffffffu, aa[2], o, 8);
        aa[3] |= __shfl_xor_sync(0xffffffffu, aa[3], o, 8);
    }
    if (idx == 0)
        *(uint4*)&g_adjw[(w4 * 4 + sub) * N_ + 4 * ip] = make_uint4(aa[0], aa[1], aa[2], aa[3]);
}

// ---------------- kernel 3: warp-specialized softmax + HMMA, cp.async staging ----------------
#define OFF_P0   0
#define OFF_P1   17408
#define OFF_H0   34816
#define OFF_H1   43520
#define OFF_EJ   52224     // 2 x 512B
#define OFF_ADJ  53248     // 2 x 1024B
#define OFF_ZSM  55296     // 512B
#define OFF_ZF   55808     // 256B
#define OFF_MBAR 56064     // 4 x 8B
#define ATTN_SMEM 56192

__device__ __forceinline__ void ldsm_x4(unsigned addr, unsigned& a0, unsigned& a1,
                                        unsigned& a2, unsigned& a3) {
    asm volatile("ldmatrix.sync.aligned.m8n8.x4.shared.b16 {%0,%1,%2,%3}, [%4];"
                 : "=r"(a0), "=r"(a1), "=r"(a2), "=r"(a3) : "r"(addr));
}
__device__ __forceinline__ void mma16816(float* d, const unsigned* a, unsigned b0, unsigned b1) {
    asm volatile("mma.sync.aligned.m16n8k16.row.col.f32.f16.f16.f32 "
                 "{%0,%1,%2,%3}, {%4,%5,%6,%7}, {%8,%9}, {%0,%1,%2,%3};"
                 : "+f"(d[0]), "+f"(d[1]), "+f"(d[2]), "+f"(d[3])
                 : "r"(a[0]), "r"(a[1]), "r"(a[2]), "r"(a[3]), "r"(b0), "r"(b1));
}
__device__ __forceinline__ void mbar_wait(unsigned mb, unsigned parity) {
    asm volatile(
        "{\n\t.reg .pred P1;\n\t"
        "WL_%=:\n\t"
        "mbarrier.try_wait.parity.acquire.cta.shared::cta.b64 P1, [%0], %1, 0x989680;\n\t"
        "@P1 bra.uni WD_%=;\n\t"
        "bra.uni WL_%=;\n\t"
        "WD_%=:\n\t}"
        :: "r"(mb), "r"(parity) : "memory");
}
__device__ __forceinline__ void mbar_arrive(unsigned mb) {
    asm volatile("mbarrier.arrive.shared.b64 _, [%0];" :: "r"(mb) : "memory");
}

__global__ void __launch_bounds__(256, 4) k_attn(float* __restrict__ out) {
    extern __shared__ char smc[];
    const unsigned sb = smem_u32(smc);
    float* zsm = (float*)(smc + OFF_ZSM);
    float* zf  = (float*)(smc + OFF_ZF);

    const int t = threadIdx.x, wid = t >> 5, lane = t & 31;
    const int i0 = blockIdx.x * 64, hh = blockIdx.y, b = blockIdx.z;

    const unsigned mb_pfull0  = sb + OFF_MBAR;
    const unsigned mb_pfull1  = sb + OFF_MBAR + 8;
    const unsigned mb_pempty0 = sb + OFF_MBAR + 16;
    const unsigned mb_pempty1 = sb + OFF_MBAR + 24;

    if (t == 0) {
        asm volatile("mbarrier.init.shared.b64 [%0], %1;" :: "r"(mb_pfull0),  "r"(128u) : "memory");
        asm volatile("mbarrier.init.shared.b64 [%0], %1;" :: "r"(mb_pfull1),  "r"(128u) : "memory");
        asm volatile("mbarrier.init.shared.b64 [%0], %1;" :: "r"(mb_pempty0), "r"(128u) : "memory");
        asm volatile("mbarrier.init.shared.b64 [%0], %1;" :: "r"(mb_pempty1), "r"(128u) : "memory");
    }
    __syncthreads();

    if (wid < 4) {
        // ================= PRODUCERS (t in [0,128)) =================
        const int iA = t >> 1, jq2 = t & 1;
        const float ei_r = g_ei[(b * N_ + i0 + iA) * H_ + hh];
        float zpart = 0.f;
        const unsigned short* hp = g_hp + ((size_t)((b * H_ + hh) * HD_)) * N_;

        #define ISSUE_COPIES(tl, buf)                                                       \
        do {                                                                                \
            const int jj0 = (tl) * 128;                                                     \
            const unsigned offH_ = (buf) ? OFF_H1 : OFF_H0;                                 \
            _Pragma("unroll")                                                               \
            for (int r = 0; r < 4; r++) {                                                   \
                int id = t + r * 128;                                                       \
                int d = id >> 4, q = id & 15;                                               \
                CP16(sb + offH_ + d * 272 + q * 16, &hp[(size_t)d * N_ + jj0 + q * 8]);     \
            }                                                                               \
            CP4(sb + OFF_EJ + (buf) * 512 + t * 4, &g_ej[(b * N_ + jj0 + t) * H_ + hh]);    \
            if (t < 64) {                                                                   \
                int jwl = t >> 4, c4 = t & 15;                                              \
                CP16(sb + OFF_ADJ + (buf) * 1024 + (jwl * 64 + c4 * 4) * 4,                 \
                     &g_adjw[((jj0 >> 5) + jwl) * N_ + i0 + c4 * 4]);                       \
            }                                                                               \
            asm volatile("cp.async.commit_group;" ::: "memory");                            \
        } while (0)

        ISSUE_COPIES(0, 0);

        for (int tile = 0; tile < 16; tile++) {
            const int cur = tile & 1;

            if (tile + 1 < 16) {
                if (tile + 1 >= 2)
                    mbar_wait((tile & 1) ? mb_pempty0 : mb_pempty1,   // buffer (tile+1)&1
                              (unsigned)((((tile + 1) >> 1) - 1) & 1));
                ISSUE_COPIES(tile + 1, (tile + 1) & 1);
                asm volatile("cp.async.wait_group 1;" ::: "memory");
            } else {
                asm volatile("cp.async.wait_group 0;" ::: "memory");
            }
            asm volatile("bar.sync 1, 128;" ::: "memory");

            // scores: 64 j per thread
            {
                const unsigned* aw = (const unsigned*)(smc + OFF_ADJ + cur * 1024);
                const unsigned w0 = aw[(jq2 * 2 + 0) * 64 + iA];
                const unsigned w1 = aw[(jq2 * 2 + 1) * 64 + iA];
                const float* ejq = (const float*)(smc + OFF_EJ + cur * 512) + jq2 * 64;
                char* phiRow = smc + (cur ? OFF_P1 : OFF_P0) + iA * 272 + jq2 * 128;
                #pragma unroll 8
                for (int q = 0; q < 16; q++) {
                    const unsigned w = (q < 8) ? w0 : w1;
                    const int bit = (q & 7) * 4;
                    float4 ev = *(const float4*)&ejq[q * 4];
                    float s0 = ei_r + ev.x, s1 = ei_r + ev.y;
                    float s2 = ei_r + ev.z, s3 = ei_r + ev.w;
                    s0 = fmaxf(s0, 0.2f * s0); s1 = fmaxf(s1, 0.2f * s1);
                    s2 = fmaxf(s2, 0.2f * s2); s3 = fmaxf(s3, 0.2f * s3);
                    float e0 = ex2f(s0), e1 = ex2f(s1), e2 = ex2f(s2), e3 = ex2f(s3);
                    e0 = ((w >> (bit + 0)) & 1u) ? e0 : 0.f;
                    e1 = ((w >> (bit + 1)) & 1u) ? e1 : 0.f;
                    e2 = ((w >> (bit + 2)) & 1u) ? e2 : 0.f;
                    e3 = ((w >> (bit + 3)) & 1u) ? e3 : 0.f;
                    zpart += (e0 + e1) + (e2 + e3);
                    *(uint2*)(phiRow + q * 8) = make_uint2(pk_f16x2(e0, e1), pk_f16x2(e2, e3));
                }
            }
            mbar_arrive(cur ? mb_pfull1 : mb_pfull0);
        }

        zsm[jq2 * 64 + iA] = zpart;
        asm volatile("bar.sync 1, 128;" ::: "memory");
        if (t < 64) zf[t] = 1.0f / (zsm[t] + zsm[64 + t]);
        __syncthreads();       // join with consumers
    } else {
        // ================= CONSUMERS (warps 4-7) =================
        const int w = wid - 4;
        const unsigned aAr = (unsigned)(w * 16 + (lane & 15)) * 272u + ((lane >> 4) & 1) * 16u;
        const unsigned bRow = (unsigned)((lane & 7) + ((lane >> 4) & 1) * 8) * 272u
                            + ((lane >> 3) & 1) * 16u;
        float dacc[4][4];
        #pragma unroll
        for (int nb = 0; nb < 4; nb++)
            #pragma unroll
            for (int k = 0; k < 4; k++) dacc[nb][k] = 0.f;

        for (int tile = 0; tile < 16; tile++) {
            const int cur = tile & 1;
            mbar_wait(cur ? mb_pfull1 : mb_pfull0, (unsigned)((tile >> 1) & 1));
            const unsigned aA  = sb + (cur ? OFF_P1 : OFF_P0) + aAr;
            const unsigned aB0 = sb + (cur ? OFF_H1 : OFF_H0) + bRow;
            const unsigned aB1 = aB0 + 16u * 272u;
            #pragma unroll
            for (int ks = 0; ks < 8; ks++) {
                const unsigned off = (unsigned)ks * 32u;
                unsigned a[4], b0, b1, c0, c1, e0, e1, f0, f1;
                ldsm_x4(aA + off, a[0], a[1], a[2], a[3]);
                ldsm_x4(aB0 + off, b0, b1, c0, c1);
                ldsm_x4(aB1 + off, e0, e1, f0, f1);
                mma16816(dacc[0], a, b0, b1);
                mma16816(dacc[1], a, c0, c1);
                mma16816(dacc[2], a, e0, e1);
                mma16816(dacc[3], a, f0, f1);
            }
            mbar_arrive(cur ? mb_pempty1 : mb_pempty0);
        }

        __syncthreads();       // join: zf ready

        const int gid = lane >> 2, tig = lane & 3;
        const float zi0 = zf[w * 16 + gid], zi1 = zf[w * 16 + gid + 8];
        const size_t r0 = (size_t)(b * N_) + i0 + w * 16 + gid;
        float* o0 = out + r0 * DIN + hh * HD_ + 2 * tig;
        float* o1 = o0 + 8 * DIN;
        #pragma unroll
        for (int nb = 0; nb < 4; nb++) {
            *(float2*)(o0 + nb * 8) = make_float2(dacc[nb][0] * zi0, dacc[nb][1] * zi0);
            *(float2*)(o1 + nb * 8) = make_float2(dacc[nb][2] * zi1, dacc[nb][3] * zi1);
        }
    }
}

// ---------------- launch ----------------
extern "C" void kernel_launch(void* const* d_in, const int* in_sizes, int n_in,
                              void* d_out, int out_size) {
    const float* x   = (const float*)d_in[0];
    const int*   adj = (const int*)d_in[1];
    const float* W   = (const float*)d_in[2];
    const float* a   = (const float*)d_in[3];
    float*       out = (float*)d_out;

    cudaFuncSetAttribute(k_gemm, cudaFuncAttributeMaxDynamicSharedMemorySize, GEMM_SMEM);
    cudaFuncSetAttribute(k_attn, cudaFuncAttributeMaxDynamicSharedMemorySize, ATTN_SMEM);

    k_gemm<<<B_ * N_ / 64, 256, GEMM_SMEM>>>(x, W);
    k_eij <<<B_ * N_ / 8, 256>>>(a);
    k_pack<<<1024, 256>>>(adj);
    k_attn<<<dim3(N_ / 64, H_, B_), 256, ATTN_SMEM>>>(out);
}

// round 10
// speedup vs baseline: 2.9781x; 1.0342x over previous
#include <cuda_runtime.h>
#include <cuda_fp16.h>
#include <cstdint>

#define B_   4
#define N_   2048
#define DIN  128
#define H_   4
#define HD_  32
#define LOG2E 1.4426950408889634f

// ---------------- scratch (no allocs allowed) ----------------
__device__ float    g_ei[B_ * N_ * H_];      // pre-scaled by log2e
__device__ float    g_ej[B_ * N_ * H_];
__device__ unsigned g_adjw[(N_ / 32) * N_];  // [jw][i]  transposed bitmask
// h f16, transposed per (b,h): [b][h][d][j]
__device__ __align__(16) unsigned short g_hp[B_ * H_ * HD_ * N_];

__device__ __forceinline__ float ex2f(float x) {
    float r; asm("ex2.approx.ftz.f32 %0, %1;" : "=f"(r) : "f"(x)); return r;
}
__device__ __forceinline__ unsigned pk_f16x2(float f0, float f1) {
    unsigned r;
    asm("cvt.rn.f16x2.f32 %0, %1, %2;" : "=r"(r) : "f"(f1), "f"(f0));
    return r;
}
__device__ __forceinline__ unsigned smem_u32(const void* p) {
    unsigned a;
    asm("{ .reg .u64 t; cvta.to.shared.u64 t, %1; cvt.u32.u64 %0, t; }" : "=r"(a) : "l"(p));
    return a;
}
#define CP16(dst, src) asm volatile("cp.async.cg.shared.global [%0], [%1], 16;" :: "r"(dst), "l"(src) : "memory")
#define CP4(dst, src)  asm volatile("cp.async.ca.shared.global [%0], [%1], 4;"  :: "r"(dst), "l"(src) : "memory")

// ---------------- kernel 1: h = x@W^T -> {f16 plane, ei, ej} (g_h never stored) ----------------
#define WT_STRIDE 132
#define GEMM_SMEM ((128 * WT_STRIDE + 64 * 128) * 4)
__global__ void k_gemm(const float* __restrict__ x, const float* __restrict__ W,
                       const float* __restrict__ a) {
    extern __shared__ float sm[];
    float* Wt = sm;
    float* xs = sm + 128 * WT_STRIDE;
    const int t = threadIdx.x;
    const int row0 = blockIdx.x * 64;
    for (int idx = t; idx < 128 * 128; idx += 256) {
        int c = idx >> 7, k = idx & 127;
        Wt[k * WT_STRIDE + c] = W[idx];
    }
    for (int idx = t; idx < 64 * 128 / 4; idx += 256)
        *(float4*)&xs[idx * 4] = *(const float4*)&x[(size_t)row0 * 128 + idx * 4];
    __syncthreads();
    const int rg = t >> 5, cg = t & 31;
    float acc[8][4];
    #pragma unroll
    for (int r = 0; r < 8; r++) { acc[r][0]=acc[r][1]=acc[r][2]=acc[r][3]=0.f; }
    #pragma unroll 4
    for (int k = 0; k < 128; k++) {
        float4 wv = *(const float4*)&Wt[k * WT_STRIDE + cg * 4];
        #pragma unroll
        for (int r = 0; r < 8; r++) {
            float xv = xs[(rg * 8 + r) * 128 + k];
            acc[r][0] = fmaf(xv, wv.x, acc[r][0]);
            acc[r][1] = fmaf(xv, wv.y, acc[r][1]);
            acc[r][2] = fmaf(xv, wv.z, acc[r][2]);
            acc[r][3] = fmaf(xv, wv.w, acc[r][3]);
        }
    }

    // ---- fused ei/ej: per-lane partial dot with a1/a2, 8-lane shuffle reduce ----
    {
        const int head = cg >> 3, din = (cg & 7) * 4;
        float a1c[4], a2c[4];
        #pragma unroll
        for (int c = 0; c < 4; c++) {
            a1c[c] = a[head * 64 + din + c] * LOG2E;
            a2c[c] = a[head * 64 + 32 + din + c] * LOG2E;
        }
        #pragma unroll
        for (int r = 0; r < 8; r++) {
            float p1 = acc[r][0]*a1c[0] + acc[r][1]*a1c[1] + acc[r][2]*a1c[2] + acc[r][3]*a1c[3];
            float p2 = acc[r][0]*a2c[0] + acc[r][1]*a2c[1] + acc[r][2]*a2c[2] + acc[r][3]*a2c[3];
            #pragma unroll
            for (int o = 1; o < 8; o <<= 1) {
                p1 += __shfl_xor_sync(0xffffffffu, p1, o, 8);
                p2 += __shfl_xor_sync(0xffffffffu, p2, o, 8);
            }
            if ((cg & 7) == 0) {
                const int row = row0 + rg * 8 + r;
                g_ei[row * H_ + head] = p1;
                g_ej[row * H_ + head] = p2;
            }
        }
    }

    // ---- transpose to f16 plane [d][j] via smem ----
    __syncthreads();
    unsigned short* sm16 = (unsigned short*)sm;    // [128 d][72]
    #pragma unroll
    for (int r = 0; r < 8; r++) {
        const int jl = rg * 8 + r;
        #pragma unroll
        for (int c = 0; c < 4; c++)
            sm16[(cg * 4 + c) * 72 + jl] = __half_as_ushort(__float2half_rn(acc[r][c]));
    }
    __syncthreads();
    {
        const int bb = row0 >> 11, j0l = row0 & 2047;
        #pragma unroll
        for (int p = 0; p < 4; p++) {
            int idx = t + p * 256;
            int d = idx >> 3, q = idx & 7;
            uint4 v = *(uint4*)&sm16[d * 72 + q * 8];
            int hh2 = d >> 5, dd = d & 31;
            *(uint4*)&g_hp[(((size_t)bb * H_ + hh2) * HD_ + dd) * N_ + j0l + q * 8] = v;
        }
    }
}

// ---------------- kernel 2: pack adj (4 rows/warp, uint4 out) ----------------
__global__ void k_pack(const int* __restrict__ adj) {
    const int wid = threadIdx.x >> 5, lane = threadIdx.x & 31;
    const int gw = blockIdx.x * 8 + wid;
    const int ip = gw >> 4, w4 = gw & 15;
    const int sub = lane >> 3, idx = lane & 7;
    const size_t base = (size_t)(4 * ip) * N_ + w4 * 128 + sub * 32 + idx * 4;
    unsigned aa[4];
    #pragma unroll
    for (int k = 0; k < 4; k++) {
        int4 v = *(const int4*)&adj[base + (size_t)k * N_];
        aa[k] = ((v.x != 0 ? 1u : 0u) | (v.y != 0 ? 2u : 0u)
               | (v.z != 0 ? 4u : 0u) | (v.w != 0 ? 8u : 0u)) << (idx * 4);
    }
    #pragma unroll
    for (int o = 1; o < 8; o <<= 1) {
        aa[0] |= __shfl_xor_sync(0xffffffffu, aa[0], o, 8);
        aa[1] |= __shfl_xor_sync(0xffffffffu, aa[1], o, 8);
        aa[2] |= __shfl_xor_sync(0xffffffffu, aa[2], o, 8);
        aa[3] |= __shfl_xor_sync(0xffffffffu, aa[3], o, 8);
    }
    if (idx == 0)
        *(uint4*)&g_adjw[(w4 * 4 + sub) * N_ + 4 * ip] = make_uint4(aa[0], aa[1], aa[2], aa[3]);
}

// ---------------- kernel 3: warp-specialized, BI=128, 512 threads, single wave ----------------
#define OFF_P0   0          // 128 x 272
#define OFF_P1   34816
#define OFF_H0   69632      // 32 x 272
#define OFF_H1   78336
#define OFF_EJ   87040      // 2 x 512B
#define OFF_ADJ  88064      // 2 x 2048B
#define OFF_ZSM  92160      // 1024B
#define OFF_ZF   93184      // 512B
#define OFF_MBAR 93696      // 4 x 8B
#define ATTN_SMEM 93728

__device__ __forceinline__ void ldsm_x4(unsigned addr, unsigned& a0, unsigned& a1,
                                        unsigned& a2, unsigned& a3) {
    asm volatile("ldmatrix.sync.aligned.m8n8.x4.shared.b16 {%0,%1,%2,%3}, [%4];"
                 : "=r"(a0), "=r"(a1), "=r"(a2), "=r"(a3) : "r"(addr));
}
__device__ __forceinline__ void mma16816(float* d, const unsigned* a, unsigned b0, unsigned b1) {
    asm volatile("mma.sync.aligned.m16n8k16.row.col.f32.f16.f16.f32 "
                 "{%0,%1,%2,%3}, {%4,%5,%6,%7}, {%8,%9}, {%0,%1,%2,%3};"
                 : "+f"(d[0]), "+f"(d[1]), "+f"(d[2]), "+f"(d[3])
                 : "r"(a[0]), "r"(a[1]), "r"(a[2]), "r"(a[3]), "r"(b0), "r"(b1));
}
__device__ __forceinline__ void mbar_wait(unsigned mb, unsigned parity) {
    asm volatile(
        "{\n\t.reg .pred P1;\n\t"
        "WL_%=:\n\t"
        "mbarrier.try_wait.parity.acquire.cta.shared::cta.b64 P1, [%0], %1, 0x989680;\n\t"
        "@P1 bra.uni WD_%=;\n\t"
        "bra.uni WL_%=;\n\t"
        "WD_%=:\n\t}"
        :: "r"(mb), "r"(parity) : "memory");
}
__device__ __forceinline__ void mbar_arrive(unsigned mb) {
    asm volatile("mbarrier.arrive.shared.b64 _, [%0];" :: "r"(mb) : "memory");
}

__global__ void __launch_bounds__(512, 2) k_attn(float* __restrict__ out) {
    extern __shared__ char smc[];
    const unsigned sb = smem_u32(smc);
    float* zsm = (float*)(smc + OFF_ZSM);
    float* zf  = (float*)(smc + OFF_ZF);

    const int t = threadIdx.x, wid = t >> 5, lane = t & 31;
    const int i0 = blockIdx.x * 128, hh = blockIdx.y, b = blockIdx.z;

    const unsigned mb_pfull0  = sb + OFF_MBAR;
    const unsigned mb_pfull1  = sb + OFF_MBAR + 8;
    const unsigned mb_pempty0 = sb + OFF_MBAR + 16;
    const unsigned mb_pempty1 = sb + OFF_MBAR + 24;

    if (t == 0) {
        asm volatile("mbarrier.init.shared.b64 [%0], %1;" :: "r"(mb_pfull0),  "r"(256u) : "memory");
        asm volatile("mbarrier.init.shared.b64 [%0], %1;" :: "r"(mb_pfull1),  "r"(256u) : "memory");
        asm volatile("mbarrier.init.shared.b64 [%0], %1;" :: "r"(mb_pempty0), "r"(256u) : "memory");
        asm volatile("mbarrier.init.shared.b64 [%0], %1;" :: "r"(mb_pempty1), "r"(256u) : "memory");
    }
    __syncthreads();

    if (wid < 8) {
        // ================= PRODUCERS (t in [0,256)) =================
        const int iA = t >> 1, jq2 = t & 1;            // 128 rows x 2 j-halves (64 j each)
        const float ei_r = g_ei[(b * N_ + i0 + iA) * H_ + hh];
        float zpart = 0.f;
        const unsigned short* hp = g_hp + ((size_t)((b * H_ + hh) * HD_)) * N_;

        #define ISSUE_COPIES(tl, buf)                                                       \
        do {                                                                                \
            const int jj0 = (tl) * 128;                                                     \
            const unsigned offH_ = (buf) ? OFF_H1 : OFF_H0;                                 \
            _Pragma("unroll")                                                               \
            for (int r = 0; r < 2; r++) {                                                   \
                int id = t + r * 256;                                                       \
                int d = id >> 4, q = id & 15;                                               \
                CP16(sb + offH_ + d * 272 + q * 16, &hp[(size_t)d * N_ + jj0 + q * 8]);     \
            }                                                                               \
            if (t < 128)                                                                    \
                CP4(sb + OFF_EJ + (buf) * 512 + t * 4, &g_ej[(b * N_ + jj0 + t) * H_ + hh]); \
            if (t < 128) {                                                                  \
                int jwl = t >> 5, il4 = (t & 31) * 4;                                       \
                CP16(sb + OFF_ADJ + (buf) * 2048 + (jwl * 128 + il4) * 4,                   \
                     &g_adjw[((jj0 >> 5) + jwl) * N_ + i0 + il4]);                          \
            }                                                                               \
            asm volatile("cp.async.commit_group;" ::: "memory");                            \
        } while (0)

        ISSUE_COPIES(0, 0);

        for (int tile = 0; tile < 16; tile++) {
            const int cur = tile & 1;

            if (tile + 1 < 16) {
                if (tile + 1 >= 2)
                    mbar_wait((tile & 1) ? mb_pempty0 : mb_pempty1,
                              (unsigned)((((tile + 1) >> 1) - 1) & 1));
                ISSUE_COPIES(tile + 1, (tile + 1) & 1);
                asm volatile("cp.async.wait_group 1;" ::: "memory");
            } else {
                asm volatile("cp.async.wait_group 0;" ::: "memory");
            }
            asm volatile("bar.sync 1, 256;" ::: "memory");

            // scores: 64 j per thread
            {
                const unsigned* aw = (const unsigned*)(smc + OFF_ADJ + cur * 2048);
                const unsigned w0 = aw[(jq2 * 2 + 0) * 128 + iA];
                const unsigned w1 = aw[(jq2 * 2 + 1) * 128 + iA];
                const float* ejq = (const float*)(smc + OFF_EJ + cur * 512) + jq2 * 64;
                char* phiRow = smc + (cur ? OFF_P1 : OFF_P0) + iA * 272 + jq2 * 128;
                #pragma unroll 8
                for (int q = 0; q < 16; q++) {
                    const unsigned w = (q < 8) ? w0 : w1;
                    const int bit = (q & 7) * 4;
                    float4 ev = *(const float4*)&ejq[q * 4];
                    float s0 = ei_r + ev.x, s1 = ei_r + ev.y;
                    float s2 = ei_r + ev.z, s3 = ei_r + ev.w;
                    s0 = fmaxf(s0, 0.2f * s0); s1 = fmaxf(s1, 0.2f * s1);
                    s2 = fmaxf(s2, 0.2f * s2); s3 = fmaxf(s3, 0.2f * s3);
                    float e0 = ex2f(s0), e1 = ex2f(s1), e2 = ex2f(s2), e3 = ex2f(s3);
                    e0 = ((w >> (bit + 0)) & 1u) ? e0 : 0.f;
                    e1 = ((w >> (bit + 1)) & 1u) ? e1 : 0.f;
                    e2 = ((w >> (bit + 2)) & 1u) ? e2 : 0.f;
                    e3 = ((w >> (bit + 3)) & 1u) ? e3 : 0.f;
                    zpart += (e0 + e1) + (e2 + e3);
                    *(uint2*)(phiRow + q * 8) = make_uint2(pk_f16x2(e0, e1), pk_f16x2(e2, e3));
                }
            }
            mbar_arrive(cur ? mb_pfull1 : mb_pfull0);
        }

        zsm[jq2 * 128 + iA] = zpart;
        asm volatile("bar.sync 1, 256;" ::: "memory");
        if (t < 128) zf[t] = 1.0f / (zsm[t] + zsm[128 + t]);
        __syncthreads();       // join with consumers
    } else {
        // ================= CONSUMERS (warps 8-15) =================
        const int w = wid - 8;                          // m strip = w*16
        const unsigned aAr = (unsigned)(w * 16 + (lane & 15)) * 272u + ((lane >> 4) & 1) * 16u;
        const unsigned bRow = (unsigned)((lane & 7) + ((lane >> 4) & 1) * 8) * 272u
                            + ((lane >> 3) & 1) * 16u;
        float dacc[4][4];
        #pragma unroll
        for (int nb = 0; nb < 4; nb++)
            #pragma unroll
            for (int k = 0; k < 4; k++) dacc[nb][k] = 0.f;

        for (int tile = 0; tile < 16; tile++) {
            const int cur = tile & 1;
            mbar_wait(cur ? mb_pfull1 : mb_pfull0, (unsigned)((tile >> 1) & 1));
            const unsigned aA  = sb + (cur ? OFF_P1 : OFF_P0) + aAr;
            const unsigned aB0 = sb + (cur ? OFF_H1 : OFF_H0) + bRow;
            const unsigned aB1 = aB0 + 16u * 272u;
            #pragma unroll
            for (int ks = 0; ks < 8; ks++) {
                const unsigned off = (unsigned)ks * 32u;
                unsigned a[4], b0, b1, c0, c1, e0, e1, f0, f1;
                ldsm_x4(aA + off, a[0], a[1], a[2], a[3]);
                ldsm_x4(aB0 + off, b0, b1, c0, c1);
                ldsm_x4(aB1 + off, e0, e1, f0, f1);
                mma16816(dacc[0], a, b0, b1);
                mma16816(dacc[1], a, c0, c1);
                mma16816(dacc[2], a, e0, e1);
                mma16816(dacc[3], a, f0, f1);
            }
            mbar_arrive(cur ? mb_pempty1 : mb_pempty0);
        }

        __syncthreads();       // join: zf ready

        const int gid = lane >> 2, tig = lane & 3;
        const float zi0 = zf[w * 16 + gid], zi1 = zf[w * 16 + gid + 8];
        const size_t r0 = (size_t)(b * N_) + i0 + w * 16 + gid;
        float* o0 = out + r0 * DIN + hh * HD_ + 2 * tig;
        float* o1 = o0 + 8 * DIN;
        #pragma unroll
        for (int nb = 0; nb < 4; nb++) {
            *(float2*)(o0 + nb * 8) = make_float2(dacc[nb][0] * zi0, dacc[nb][1] * zi0);
            *(float2*)(o1 + nb * 8) = make_float2(dacc[nb][2] * zi1, dacc[nb][3] * zi1);
        }
    }
}

// ---------------- launch ----------------
extern "C" void kernel_launch(void* const* d_in, const int* in_sizes, int n_in,
                              void* d_out, int out_size) {
    const float* x   = (const float*)d_in[0];
    const int*   adj = (const int*)d_in[1];
    const float* W   = (const float*)d_in[2];
    const float* a   = (const float*)d_in[3];
    float*       out = (float*)d_out;

    cudaFuncSetAttribute(k_gemm, cudaFuncAttributeMaxDynamicSharedMemorySize, GEMM_SMEM);
    cudaFuncSetAttribute(k_attn, cudaFuncAttributeMaxDynamicSharedMemorySize, ATTN_SMEM);

    k_gemm<<<B_ * N_ / 64, 256, GEMM_SMEM>>>(x, W, a);
    k_pack<<<1024, 256>>>(adj);
    k_attn<<<dim3(N_ / 128, H_, B_), 512, ATTN_SMEM>>>(out);
}